// round 10
// baseline (speedup 1.0000x reference)
#include <cuda_runtime.h>
#include <cuda_fp16.h>
#include <cstdint>

// ---------------- problem constants ----------------
#define B_    32
#define DD    512
#define KK    64
#define KTOT  32768            // K*D : flattened reduction dim
#define MM    2048             // B*F_out
#define SPLIT 16
#define KPER  (KTOT / SPLIT)   // 2048
#define BK    32               // k elems per pipeline stage (64 B rows, SW64)
#define NCH   (KPER / BK)      // 64
#define BM    64
#define BN    128
#define NSTG  3
#define STAGE_BYTES 12288      // A 4K + B 8K
#define GEMM_SMEM   (NSTG * STAGE_BYTES + 1024)
#define S1_SMEM     131072     // sX 64K + sC 64K

// SW64 swizzle for 64-byte rows: rotate 16B columns by ((row>>1)&3)
#define SW64C(r, cbyte)  ((cbyte) ^ ((((r) >> 1) & 3) * 16))

// ---------------- device scratch (no allocation) ----------------
__device__ __half g_A[(size_t)MM * KTOT];          // 128 MB (fp16 T)
__device__ __half g_B[(size_t)DD * KTOT];          // 32 MB  (W^T fp16)
__device__ __half g_C[(size_t)KK * 64 * 64];       // 512 KB (coeff [k][o][i] fp16)
__device__ float  g_part[(size_t)SPLIT * MM * DD]; // 64 MB

// ---------------- helpers ----------------
__device__ __forceinline__ uint32_t smem_u32(const void* p) {
    uint32_t a;
    asm("{ .reg .u64 t; cvta.to.shared.u64 t, %1; cvt.u32.u64 %0, t; }" : "=r"(a) : "l"(p));
    return a;
}
__device__ __forceinline__ void cp16(uint32_t dst, const void* src) {
    asm volatile("cp.async.cg.shared.global [%0], [%1], 16;" :: "r"(dst), "l"(src));
}
#define CP_COMMIT() asm volatile("cp.async.commit_group;" ::: "memory")
#define CP_WAIT(n)  asm volatile("cp.async.wait_group %0;" :: "n"(n) : "memory")

__device__ __forceinline__ void ldsm4(uint32_t* r, uint32_t addr) {
    asm volatile("ldmatrix.sync.aligned.m8n8.x4.shared.b16 {%0,%1,%2,%3}, [%4];"
                 : "=r"(r[0]), "=r"(r[1]), "=r"(r[2]), "=r"(r[3]) : "r"(addr));
}
__device__ __forceinline__ void mma_f16(float* c, const uint32_t* a, const uint32_t* b) {
    asm volatile(
        "mma.sync.aligned.m16n8k16.row.col.f32.f16.f16.f32 "
        "{%0,%1,%2,%3},{%4,%5,%6,%7},{%8,%9},{%0,%1,%2,%3};"
        : "+f"(c[0]), "+f"(c[1]), "+f"(c[2]), "+f"(c[3])
        : "r"(a[0]), "r"(a[1]), "r"(a[2]), "r"(a[3]), "r"(b[0]), "r"(b[1]));
}

// ---------------------------------------------------------------------------
// coeff transpose: coeff[o,i,k] f32 -> g_C[k][o][i] f16
// ---------------------------------------------------------------------------
__global__ void __launch_bounds__(256) ctrans_kernel(const float* __restrict__ coeff) {
    const int k = blockIdx.x;
    for (int idx = threadIdx.x; idx < 4096; idx += 256)
        g_C[k * 4096 + idx] = __float2half_rn(coeff[(size_t)idx * 64 + k]);
}

// ---------------------------------------------------------------------------
// W transpose + fp16: W[(k,e)][d] f32 -> g_B[d][(k,e)] f16
// ---------------------------------------------------------------------------
__global__ void __launch_bounds__(256) wsplit_kernel(const float* __restrict__ W) {
    __shared__ float s[32][33];
    const int kb = blockIdx.x;
    const int nb = blockIdx.y;
    const int tx = threadIdx.x & 31, tg = threadIdx.x >> 5;

#pragma unroll
    for (int r = 0; r < 4; ++r) {
        int kr = tg + r * 8;
        s[kr][tx] = W[(size_t)(kb * 32 + kr) * DD + nb * 32 + tx];
    }
    __syncthreads();
#pragma unroll
    for (int r = 0; r < 4; ++r) {
        int nr = tg + r * 8;
        g_B[(size_t)(nb * 32 + nr) * KTOT + kb * 32 + tx] = __float2half_rn(s[tx][nr]);
    }
}

// ---------------------------------------------------------------------------
// Stage 1 (tensorized): T[b*64+o][k*512+e] = sum_i coeff[o,i,k]*x[b,i,e] -> f16
// ---------------------------------------------------------------------------
__global__ void __launch_bounds__(256, 1) stage1_mma_kernel(const float* __restrict__ x) {
    extern __shared__ char smem[];
    const uint32_t sb  = smem_u32(smem);
    const uint32_t sxb = sb;
    const uint32_t scb = sb + 65536;
    const int tid = threadIdx.x, lane = tid & 31, wid = tid >> 5;
    const int k = blockIdx.x * 8 + wid;
    const int b = blockIdx.y;

    const float* xb = x + (size_t)b * 64 * 512;
#pragma unroll 4
    for (int n = 0; n < 32; ++n) {
        int g = n * 256 + tid;
        int i = g >> 7, e = (g & 127) * 4;
        float4 v = *(const float4*)&xb[i * 512 + e];
        __half h[4] = {__float2half_rn(v.x), __float2half_rn(v.y),
                       __float2half_rn(v.z), __float2half_rn(v.w)};
#pragma unroll
        for (int j = 0; j < 4; ++j) {
            uint32_t off = (e + j) * 128 + ((i * 2) ^ (((e + j) & 7) * 16));
            *(__half*)(smem + off) = h[j];
        }
    }
    {
        const __half* gc = g_C + (size_t)k * 4096;
#pragma unroll
        for (int n = 0; n < 16; ++n) {
            int idx = n * 32 + lane;
            int o = idx >> 3, c8 = idx & 7;
            uint32_t off = 65536 + wid * 8192 + o * 128 + ((c8 * 16) ^ ((o & 7) * 16));
            *(int4*)(smem + off) = *(const int4*)(gc + o * 64 + c8 * 8);
        }
    }
    __syncthreads();

    const int a_row  = (lane & 7) | (((lane >> 3) & 1) << 3);
    const int a_k16b = (lane >> 4) * 16;
    const int b_nr   = (lane & 7) | (((lane >> 4) & 1) << 3);
    const int b_k16b = ((lane >> 3) & 1) * 16;

    uint32_t a[4][4][4];
#pragma unroll
    for (int ot = 0; ot < 4; ++ot)
#pragma unroll
        for (int k16 = 0; k16 < 4; ++k16) {
            int r = ot * 16 + a_row;
            uint32_t off = scb + wid * 8192 + r * 128 + ((k16 * 32 + a_k16b) ^ ((r & 7) * 16));
            ldsm4(a[ot][k16], off);
        }

    __half* gOut = g_A + (size_t)(b * 64) * KTOT + (size_t)k * 512;

#pragma unroll 1
    for (int et = 0; et < 16; ++et) {
        float acc[4][4][4];
#pragma unroll
        for (int ot = 0; ot < 4; ++ot)
#pragma unroll
            for (int nt = 0; nt < 4; ++nt)
#pragma unroll
                for (int j = 0; j < 4; ++j) acc[ot][nt][j] = 0.0f;

#pragma unroll
        for (int k16 = 0; k16 < 4; ++k16) {
            uint32_t bb[2][4];
#pragma unroll
            for (int p = 0; p < 2; ++p) {
                int nrow = et * 32 + p * 16 + b_nr;
                uint32_t off = sxb + nrow * 128 + ((k16 * 32 + b_k16b) ^ ((nrow & 7) * 16));
                ldsm4(bb[p], off);
            }
#pragma unroll
            for (int ot = 0; ot < 4; ++ot)
#pragma unroll
                for (int nt = 0; nt < 4; ++nt)
                    mma_f16(acc[ot][nt], a[ot][k16], &bb[nt >> 1][(nt & 1) * 2]);
        }
#pragma unroll
        for (int ot = 0; ot < 4; ++ot)
#pragma unroll
            for (int nt = 0; nt < 4; ++nt) {
                int o = ot * 16 + (lane >> 2);
                int e = et * 32 + nt * 8 + (lane & 3) * 2;
                *(__half2*)&gOut[(size_t)o * KTOT + e] =
                    __floats2half2_rn(acc[ot][nt][0], acc[ot][nt][1]);
                *(__half2*)&gOut[(size_t)(o + 8) * KTOT + e] =
                    __floats2half2_rn(acc[ot][nt][2], acc[ot][nt][3]);
            }
    }
}

// ---------------------------------------------------------------------------
// Stage 2: fp16 split-K GEMM, high-occupancy + good-reuse:
//  CTA 64x128, 128 threads (4 warps, warp tile 64x32, 1m x 4n), BK=32 (SW64),
//  NSTG=3 x 12KB, <=102 regs -> 5 CTAs/SM = 20 warps/SM.
//  grid (4, 32, 16) = 2048 CTAs.
// ---------------------------------------------------------------------------
__global__ void __launch_bounds__(128, 5) gemm_kernel() {
    extern __shared__ char smem[];
    const uint32_t sb = (smem_u32(smem) + 1023) & ~1023u;

    const int tid  = threadIdx.x;
    const int lane = tid & 31;
    const int wid  = tid >> 5;
    const int n0 = blockIdx.x * BN;
    const int m0 = blockIdx.y * BM;
    const size_t k0 = (size_t)blockIdx.z * KPER;
    const int warp_n = wid * 32;

    // ---- cp.async: A 64 rows x 64B, B 128 rows x 64B per stage ----
    const int rA = tid >> 1, cA = (tid & 1) * 2;      // A: 2 thr/row, 2x16B each
    const int rB = tid;                                // B: 1 thr/row, 4x16B each
    const __half* gA = g_A + (size_t)(m0 + rA) * KTOT + k0 + cA * 8;
    const __half* gB = g_B + (size_t)(n0 + rB) * KTOT + k0;

    uint32_t swzA[2], swzB[4];
#pragma unroll
    for (int j = 0; j < 2; ++j)
        swzA[j] = rA * 64 + SW64C(rA, (cA + j) * 16);
#pragma unroll
    for (int j = 0; j < 4; ++j)
        swzB[j] = 4096 + rB * 64 + SW64C(rB, j * 16);

    const int a_row  = (lane & 7) | (((lane >> 3) & 1) << 3);
    const int a_k16b = (lane >> 4) * 16;
    const int b_nr   = (lane & 7) | (((lane >> 4) & 1) << 3);
    const int b_k16b = ((lane >> 3) & 1) * 16;

    float acc[4][4][4];
#pragma unroll
    for (int mt = 0; mt < 4; ++mt)
#pragma unroll
        for (int nt = 0; nt < 4; ++nt)
#pragma unroll
            for (int j = 0; j < 4; ++j) acc[mt][nt][j] = 0.0f;

    auto load_stage = [&](int c, int s) {
        const uint32_t base = sb + s * STAGE_BYTES;
        const int ke = c * BK;
#pragma unroll
        for (int j = 0; j < 2; ++j)
            cp16(base + swzA[j], gA + ke + j * 8);
#pragma unroll
        for (int j = 0; j < 4; ++j)
            cp16(base + swzB[j], gB + ke + j * 8);
        CP_COMMIT();
    };

    load_stage(0, 0);
    load_stage(1, 1);

    int s = 0;
    for (int c = 0; c < NCH; ++c) {
        if (c + 1 < NCH) { CP_WAIT(1); } else { CP_WAIT(0); }
        __syncthreads();
        if (c + 2 < NCH) load_stage(c + 2, (c + 2) % NSTG);

        const uint32_t Ab = sb + s * STAGE_BYTES;
        const uint32_t Bb = Ab + 4096;

#pragma unroll
        for (int k16 = 0; k16 < 2; ++k16) {
            uint32_t a[4][4], bb[2][4];
#pragma unroll
            for (int mt = 0; mt < 4; ++mt) {
                int r = mt * 16 + a_row;
                ldsm4(a[mt], Ab + r * 64 + SW64C(r, k16 * 32 + a_k16b));
            }
#pragma unroll
            for (int p = 0; p < 2; ++p) {
                int n = warp_n + p * 16 + b_nr;
                ldsm4(bb[p], Bb + n * 64 + SW64C(n, k16 * 32 + b_k16b));
            }
#pragma unroll
            for (int mt = 0; mt < 4; ++mt)
#pragma unroll
                for (int nt = 0; nt < 4; ++nt)
                    mma_f16(acc[mt][nt], a[mt], &bb[nt >> 1][(nt & 1) * 2]);
        }
        s = (s + 1 == NSTG) ? 0 : s + 1;
    }

    float* Cp = g_part + (size_t)blockIdx.z * MM * DD;
#pragma unroll
    for (int mt = 0; mt < 4; ++mt)
#pragma unroll
        for (int nt = 0; nt < 4; ++nt) {
            int r    = m0 + mt * 16 + (lane >> 2);
            int ccol = n0 + warp_n + nt * 8 + (lane & 3) * 2;
            *(float2*)&Cp[(size_t)r * DD + ccol] =
                make_float2(acc[mt][nt][0], acc[mt][nt][1]);
            *(float2*)&Cp[(size_t)(r + 8) * DD + ccol] =
                make_float2(acc[mt][nt][2], acc[mt][nt][3]);
        }
}

// ---------------------------------------------------------------------------
// Reduce split-K partials
// ---------------------------------------------------------------------------
__global__ void __launch_bounds__(256) reduce_kernel(float* __restrict__ out) {
    const int idx = blockIdx.x * 256 + threadIdx.x;
    const float4* p = (const float4*)g_part;
    float4 s = p[idx];
#pragma unroll
    for (int sp = 1; sp < SPLIT; ++sp) {
        float4 v = p[(size_t)sp * (MM * DD / 4) + idx];
        s.x += v.x; s.y += v.y; s.z += v.z; s.w += v.w;
    }
    ((float4*)out)[idx] = s;
}

extern "C" void kernel_launch(void* const* d_in, const int* in_sizes, int n_in,
                              void* d_out, int out_size) {
    const float* x     = (const float*)d_in[0];  // [32,64,512]
    const float* w     = (const float*)d_in[1];  // [64,512,512]
    const float* coeff = (const float*)d_in[2];  // [64,64,64]
    float* out = (float*)d_out;                  // [32,64,512]

    cudaFuncSetAttribute(gemm_kernel,       cudaFuncAttributeMaxDynamicSharedMemorySize, GEMM_SMEM);
    cudaFuncSetAttribute(stage1_mma_kernel, cudaFuncAttributeMaxDynamicSharedMemorySize, S1_SMEM);

    ctrans_kernel<<<KK, 256>>>(coeff);
    wsplit_kernel<<<dim3(KTOT / 32, DD / 32), 256>>>(w);
    stage1_mma_kernel<<<dim3(KK / 8, B_), 256, S1_SMEM>>>(x);
    gemm_kernel<<<dim3(DD / BN, MM / BM, SPLIT), 128, GEMM_SMEM>>>();
    reduce_kernel<<<(MM * DD / 4) / 256, 256>>>(out);
}

// round 12
// speedup vs baseline: 1.1192x; 1.1192x over previous
#include <cuda_runtime.h>
#include <cuda_fp16.h>
#include <cstdint>

// ---------------- problem constants ----------------
#define B_    32
#define DD    512
#define KK    64
#define KTOT  32768            // K*D : flattened reduction dim
#define MM    2048             // B*F_out
#define SPLIT 8
#define KPER  (KTOT / SPLIT)   // 4096
#define BK    64               // k elems per chunk
#define NCH   (KPER / BK)      // 64
#define BM    64
#define BN    128
#define NSTG  3
#define STAGE_BYTES 16384      // B only: 128 rows x 128 B
#define GEMM_SMEM   (NSTG * STAGE_BYTES + 1024)
#define S1_SMEM     131072     // sX 64K + sC 64K

// ---------------- device scratch (no allocation) ----------------
// g_A: MMA-fragment-block layout. Block (m16-tile mt, k16-tile kt):
//   uint4 index (mt*2048 + kt)*32 + lane ; uint4 = {a0,a1,a2,a3} of the a-frag.
__device__ __half g_A[(size_t)MM * KTOT];          // 128 MB
__device__ __half g_B[(size_t)DD * KTOT];          // 32 MB  (W^T fp16, row-major [d][k,e])
__device__ __half g_C[(size_t)KK * 64 * 64];       // 512 KB (coeff [k][o][i] fp16)
__device__ float  g_part[(size_t)SPLIT * MM * DD]; // 32 MB

// ---------------- helpers ----------------
__device__ __forceinline__ uint32_t smem_u32(const void* p) {
    uint32_t a;
    asm("{ .reg .u64 t; cvta.to.shared.u64 t, %1; cvt.u32.u64 %0, t; }" : "=r"(a) : "l"(p));
    return a;
}
__device__ __forceinline__ void cp16(uint32_t dst, const void* src) {
    asm volatile("cp.async.cg.shared.global [%0], [%1], 16;" :: "r"(dst), "l"(src));
}
#define CP_COMMIT() asm volatile("cp.async.commit_group;" ::: "memory")
#define CP_WAIT(n)  asm volatile("cp.async.wait_group %0;" :: "n"(n) : "memory")

__device__ __forceinline__ void ldsm4(uint32_t* r, uint32_t addr) {
    asm volatile("ldmatrix.sync.aligned.m8n8.x4.shared.b16 {%0,%1,%2,%3}, [%4];"
                 : "=r"(r[0]), "=r"(r[1]), "=r"(r[2]), "=r"(r[3]) : "r"(addr));
}
__device__ __forceinline__ void mma_f16(float* c, const uint32_t* a, const uint32_t* b) {
    asm volatile(
        "mma.sync.aligned.m16n8k16.row.col.f32.f16.f16.f32 "
        "{%0,%1,%2,%3},{%4,%5,%6,%7},{%8,%9},{%0,%1,%2,%3};"
        : "+f"(c[0]), "+f"(c[1]), "+f"(c[2]), "+f"(c[3])
        : "r"(a[0]), "r"(a[1]), "r"(a[2]), "r"(a[3]), "r"(b[0]), "r"(b[1]));
}
__device__ __forceinline__ uint32_t f2h2(float a, float b) {
    __half2 h = __floats2half2_rn(a, b);
    return *reinterpret_cast<uint32_t*>(&h);
}

// ---------------------------------------------------------------------------
// coeff transpose: coeff[o,i,k] f32 -> g_C[k][o][i] f16
// ---------------------------------------------------------------------------
__global__ void __launch_bounds__(256) ctrans_kernel(const float* __restrict__ coeff) {
    const int k = blockIdx.x;
    for (int idx = threadIdx.x; idx < 4096; idx += 256)
        g_C[k * 4096 + idx] = __float2half_rn(coeff[(size_t)idx * 64 + k]);
}

// ---------------------------------------------------------------------------
// W transpose + fp16: W[(k,e)][d] f32 -> g_B[d][(k,e)] f16
// ---------------------------------------------------------------------------
__global__ void __launch_bounds__(256) wsplit_kernel(const float* __restrict__ W) {
    __shared__ float s[32][33];
    const int kb = blockIdx.x;
    const int nb = blockIdx.y;
    const int tx = threadIdx.x & 31, tg = threadIdx.x >> 5;

#pragma unroll
    for (int r = 0; r < 4; ++r) {
        int kr = tg + r * 8;
        s[kr][tx] = W[(size_t)(kb * 32 + kr) * DD + nb * 32 + tx];
    }
    __syncthreads();
#pragma unroll
    for (int r = 0; r < 4; ++r) {
        int nr = tg + r * 8;
        g_B[(size_t)(nb * 32 + nr) * KTOT + kb * 32 + tx] = __float2half_rn(s[tx][nr]);
    }
}

// ---------------------------------------------------------------------------
// Stage 1 (tensorized): T[b*64+o][k*512+e] = sum_i coeff[o,i,k]*x[b,i,e]
// Output stored as MMA a-fragments (c-frag pairs == a-frag): STG.128 per
// (m16, k16) block -> perfectly coalesced 512B warp stores.
// ---------------------------------------------------------------------------
__global__ void __launch_bounds__(256, 1) stage1_mma_kernel(const float* __restrict__ x) {
    extern __shared__ char smem[];
    const uint32_t sb  = smem_u32(smem);
    const uint32_t sxb = sb;
    const uint32_t scb = sb + 65536;
    const int tid = threadIdx.x, lane = tid & 31, wid = tid >> 5;
    const int k = blockIdx.x * 8 + wid;
    const int b = blockIdx.y;

    const float* xb = x + (size_t)b * 64 * 512;
#pragma unroll 4
    for (int n = 0; n < 32; ++n) {
        int g = n * 256 + tid;
        int i = g >> 7, e = (g & 127) * 4;
        float4 v = *(const float4*)&xb[i * 512 + e];
        __half h[4] = {__float2half_rn(v.x), __float2half_rn(v.y),
                       __float2half_rn(v.z), __float2half_rn(v.w)};
#pragma unroll
        for (int j = 0; j < 4; ++j) {
            uint32_t off = (e + j) * 128 + ((i * 2) ^ (((e + j) & 7) * 16));
            *(__half*)(smem + off) = h[j];
        }
    }
    {
        const __half* gc = g_C + (size_t)k * 4096;
#pragma unroll
        for (int n = 0; n < 16; ++n) {
            int idx = n * 32 + lane;
            int o = idx >> 3, c8 = idx & 7;
            uint32_t off = 65536 + wid * 8192 + o * 128 + ((c8 * 16) ^ ((o & 7) * 16));
            *(int4*)(smem + off) = *(const int4*)(gc + o * 64 + c8 * 8);
        }
    }
    __syncthreads();

    const int a_row  = (lane & 7) | (((lane >> 3) & 1) << 3);
    const int a_k16b = (lane >> 4) * 16;
    const int b_nr   = (lane & 7) | (((lane >> 4) & 1) << 3);
    const int b_k16b = ((lane >> 3) & 1) * 16;

    uint32_t a[4][4][4];
#pragma unroll
    for (int ot = 0; ot < 4; ++ot)
#pragma unroll
        for (int k16 = 0; k16 < 4; ++k16) {
            int r = ot * 16 + a_row;
            uint32_t off = scb + wid * 8192 + r * 128 + ((k16 * 32 + a_k16b) ^ ((r & 7) * 16));
            ldsm4(a[ot][k16], off);
        }

    uint4* aOut = (uint4*)g_A;

#pragma unroll 1
    for (int et = 0; et < 16; ++et) {
        float acc[4][4][4];
#pragma unroll
        for (int ot = 0; ot < 4; ++ot)
#pragma unroll
            for (int nt = 0; nt < 4; ++nt)
#pragma unroll
                for (int j = 0; j < 4; ++j) acc[ot][nt][j] = 0.0f;

#pragma unroll
        for (int k16 = 0; k16 < 4; ++k16) {
            uint32_t bb[2][4];
#pragma unroll
            for (int p = 0; p < 2; ++p) {
                int nrow = et * 32 + p * 16 + b_nr;
                uint32_t off = sxb + nrow * 128 + ((k16 * 32 + b_k16b) ^ ((nrow & 7) * 16));
                ldsm4(bb[p], off);
            }
#pragma unroll
            for (int ot = 0; ot < 4; ++ot)
#pragma unroll
                for (int nt = 0; nt < 4; ++nt)
                    mma_f16(acc[ot][nt], a[ot][k16], &bb[nt >> 1][(nt & 1) * 2]);
        }

        // store as a-frag blocks: (m16 tile = b*4+ot, k16 tile = k*32+et*2+ntp)
#pragma unroll
        for (int ot = 0; ot < 4; ++ot) {
            const size_t mt = (size_t)(b * 4 + ot);
#pragma unroll
            for (int ntp = 0; ntp < 2; ++ntp) {
                uint4 v;
                v.x = f2h2(acc[ot][2 * ntp][0],     acc[ot][2 * ntp][1]);
                v.y = f2h2(acc[ot][2 * ntp][2],     acc[ot][2 * ntp][3]);
                v.z = f2h2(acc[ot][2 * ntp + 1][0], acc[ot][2 * ntp + 1][1]);
                v.w = f2h2(acc[ot][2 * ntp + 1][2], acc[ot][2 * ntp + 1][3]);
                size_t kt = (size_t)k * 32 + et * 2 + ntp;
                aOut[(mt * 2048 + kt) * 32 + lane] = v;
            }
        }
    }
}

// ---------------------------------------------------------------------------
// Stage 2: fp16 split-K GEMM, crossbar-relieved:
//  A: direct LDG.128 from fragment blocks (no smem/LDSM for A), prefetched
//     one chunk ahead via two pair-slots.
//  B: cp.async SW128 smem + ldmatrix (3 stages, 16 KB each).
//  CTA 64x128, 8 warps (warp 32x32, 2m x 4n), target 3 CTAs/SM.
//  grid (4, 32, 8) = 1024 CTAs.
// ---------------------------------------------------------------------------
__global__ void __launch_bounds__(256, 3) gemm_kernel() {
    extern __shared__ char smem[];
    const uint32_t sb = (smem_u32(smem) + 1023) & ~1023u;

    const int tid  = threadIdx.x;
    const int lane = tid & 31;
    const int wid  = tid >> 5;
    const int n0 = blockIdx.x * BN;
    const int m0 = blockIdx.y * BM;
    const size_t k0 = (size_t)blockIdx.z * KPER;
    const int warp_m = (wid & 1) * 32;
    const int warp_n = (wid >> 1) * 32;

    // ---- B cp.async: 128 rows x 128 B per stage (2 threads/row, 4x16B each) ----
    const int rB = tid >> 1, cB = (tid & 1) * 4;
    const __half* gB = g_B + (size_t)(n0 + rB) * KTOT + k0 + cB * 8;  // FIX: cB in source
    uint32_t swzB[4];
#pragma unroll
    for (int j = 0; j < 4; ++j)
        swzB[j] = rB * 128 + (((cB + j) * 16) ^ ((rB & 7) * 16));

    // ---- A direct-LDG pointers (fragment blocks) ----
    const size_t mtile0 = (size_t)((m0 + warp_m) >> 4);
    const size_t kt0 = k0 >> 4;
    const uint4* aP0 = (const uint4*)g_A + (mtile0 * 2048 + kt0) * 32 + lane;
    const uint4* aP1 = (const uint4*)g_A + ((mtile0 + 1) * 2048 + kt0) * 32 + lane;

    const int b_nr   = (lane & 7) | (((lane >> 4) & 1) << 3);
    const int b_k16b = ((lane >> 3) & 1) * 16;

    float acc[2][4][4];
#pragma unroll
    for (int mt = 0; mt < 2; ++mt)
#pragma unroll
        for (int nt = 0; nt < 4; ++nt)
#pragma unroll
            for (int j = 0; j < 4; ++j) acc[mt][nt][j] = 0.0f;

    auto load_stageB = [&](int c, int s) {
        const uint32_t base = sb + s * STAGE_BYTES;
        const int ke = c * BK;
#pragma unroll
        for (int j = 0; j < 4; ++j)
            cp16(base + swzB[j], gB + ke + j * 8);
        CP_COMMIT();
    };

    // A prologue: pairs 0 and 1 (k16 0..3 of chunk 0)
    uint4 aslot[2][2][2];   // [pair-slot][k16-in-pair][mt]
#pragma unroll
    for (int s = 0; s < 2; ++s)
#pragma unroll
        for (int kk = 0; kk < 2; ++kk) {
            int kt = s * 2 + kk;
            aslot[s][kk][0] = aP0[kt * 32];
            aslot[s][kk][1] = aP1[kt * 32];
        }

    load_stageB(0, 0);
    load_stageB(1, 1);

    int s = 0;
    for (int c = 0; c < NCH; ++c) {
        if (c + 1 < NCH) { CP_WAIT(1); } else { CP_WAIT(0); }
        __syncthreads();
        if (c + 2 < NCH) load_stageB(c + 2, (c + 2) % NSTG);

        const uint32_t Bb = sb + s * STAGE_BYTES;

#pragma unroll
        for (int jp = 0; jp < 2; ++jp) {
#pragma unroll
            for (int kk = 0; kk < 2; ++kk) {
                const int k16 = jp * 2 + kk;
                uint32_t bb[2][4];
#pragma unroll
                for (int p = 0; p < 2; ++p) {
                    int n = warp_n + p * 16 + b_nr;
                    ldsm4(bb[p], Bb + n * 128 + ((k16 * 32 + b_k16b) ^ ((n & 7) * 16)));
                }
#pragma unroll
                for (int mt = 0; mt < 2; ++mt)
#pragma unroll
                    for (int nt = 0; nt < 4; ++nt)
                        mma_f16(acc[mt][nt],
                                reinterpret_cast<const uint32_t*>(&aslot[jp][kk][mt]),
                                &bb[nt >> 1][(nt & 1) * 2]);
            }
            // prefetch this pair-slot for chunk c+1 (distance = 1 chunk)
            if (c + 1 < NCH) {
                const int ktl = (c + 1) * 4 + jp * 2;
                aslot[jp][0][0] = aP0[(size_t)ktl * 32];
                aslot[jp][0][1] = aP1[(size_t)ktl * 32];
                aslot[jp][1][0] = aP0[(size_t)(ktl + 1) * 32];
                aslot[jp][1][1] = aP1[(size_t)(ktl + 1) * 32];
            }
        }
        s = (s + 1 == NSTG) ? 0 : s + 1;
    }

    float* Cp = g_part + (size_t)blockIdx.z * MM * DD;
#pragma unroll
    for (int mt = 0; mt < 2; ++mt)
#pragma unroll
        for (int nt = 0; nt < 4; ++nt) {
            int r    = m0 + warp_m + mt * 16 + (lane >> 2);
            int ccol = n0 + warp_n + nt * 8 + (lane & 3) * 2;
            *(float2*)&Cp[(size_t)r * DD + ccol] =
                make_float2(acc[mt][nt][0], acc[mt][nt][1]);
            *(float2*)&Cp[(size_t)(r + 8) * DD + ccol] =
                make_float2(acc[mt][nt][2], acc[mt][nt][3]);
        }
}

// ---------------------------------------------------------------------------
// Reduce split-K partials
// ---------------------------------------------------------------------------
__global__ void __launch_bounds__(256) reduce_kernel(float* __restrict__ out) {
    const int idx = blockIdx.x * 256 + threadIdx.x;
    const float4* p = (const float4*)g_part;
    float4 s = p[idx];
#pragma unroll
    for (int sp = 1; sp < SPLIT; ++sp) {
        float4 v = p[(size_t)sp * (MM * DD / 4) + idx];
        s.x += v.x; s.y += v.y; s.z += v.z; s.w += v.w;
    }
    ((float4*)out)[idx] = s;
}

extern "C" void kernel_launch(void* const* d_in, const int* in_sizes, int n_in,
                              void* d_out, int out_size) {
    const float* x     = (const float*)d_in[0];  // [32,64,512]
    const float* w     = (const float*)d_in[1];  // [64,512,512]
    const float* coeff = (const float*)d_in[2];  // [64,64,64]
    float* out = (float*)d_out;                  // [32,64,512]

    cudaFuncSetAttribute(gemm_kernel,       cudaFuncAttributeMaxDynamicSharedMemorySize, GEMM_SMEM);
    cudaFuncSetAttribute(stage1_mma_kernel, cudaFuncAttributeMaxDynamicSharedMemorySize, S1_SMEM);

    ctrans_kernel<<<KK, 256>>>(coeff);
    wsplit_kernel<<<dim3(KTOT / 32, DD / 32), 256>>>(w);
    stage1_mma_kernel<<<dim3(KK / 8, B_), 256, S1_SMEM>>>(x);
    gemm_kernel<<<dim3(DD / BN, MM / BM, SPLIT), 256, GEMM_SMEM>>>();
    reduce_kernel<<<(MM * DD / 4) / 256, 256>>>(out);
}

// round 13
// speedup vs baseline: 1.4825x; 1.3247x over previous
#include <cuda_runtime.h>
#include <cuda_fp16.h>
#include <cstdint>

// ---------------- problem constants ----------------
#define B_    32
#define DD    512
#define KK    64
#define KTOT  32768            // K*D : flattened reduction dim
#define MM    2048             // B*F_out
#define SPLIT 16
#define KPER  (KTOT / SPLIT)   // 2048
#define BK    64               // k elems per chunk
#define NCH   (KPER / BK)      // 32
#define BM    64
#define BN    128
#define NSTG  3
#define STAGE_BYTES 24576      // A frag-blocks 8K + B 16K
#define GEMM_SMEM   (NSTG * STAGE_BYTES + 1024)
#define S1_SMEM     131072     // sX 64K + sC 64K

// ---------------- device scratch (no allocation) ----------------
// g_A: MMA-fragment-block layout. Block (m16-tile mt, k16-tile kt):
//   uint4 index (mt*2048 + kt)*32 + lane ; uint4 = {a0,a1,a2,a3} of the a-frag.
__device__ __half g_A[(size_t)MM * KTOT];          // 128 MB
__device__ __half g_B[(size_t)DD * KTOT];          // 32 MB  (W^T fp16, row-major [d][k,e])
__device__ __half g_C[(size_t)KK * 64 * 64];       // 512 KB (coeff [k][o][i] fp16)

// ---------------- helpers ----------------
__device__ __forceinline__ uint32_t smem_u32(const void* p) {
    uint32_t a;
    asm("{ .reg .u64 t; cvta.to.shared.u64 t, %1; cvt.u32.u64 %0, t; }" : "=r"(a) : "l"(p));
    return a;
}
__device__ __forceinline__ void cp16(uint32_t dst, const void* src) {
    asm volatile("cp.async.cg.shared.global [%0], [%1], 16;" :: "r"(dst), "l"(src));
}
#define CP_COMMIT() asm volatile("cp.async.commit_group;" ::: "memory")
#define CP_WAIT(n)  asm volatile("cp.async.wait_group %0;" :: "n"(n) : "memory")

__device__ __forceinline__ void ldsm4(uint32_t* r, uint32_t addr) {
    asm volatile("ldmatrix.sync.aligned.m8n8.x4.shared.b16 {%0,%1,%2,%3}, [%4];"
                 : "=r"(r[0]), "=r"(r[1]), "=r"(r[2]), "=r"(r[3]) : "r"(addr));
}
__device__ __forceinline__ void lds128(uint32_t* r, uint32_t addr) {
    asm volatile("ld.shared.v4.u32 {%0,%1,%2,%3}, [%4];"
                 : "=r"(r[0]), "=r"(r[1]), "=r"(r[2]), "=r"(r[3]) : "r"(addr));
}
__device__ __forceinline__ void mma_f16(float* c, const uint32_t* a, const uint32_t* b) {
    asm volatile(
        "mma.sync.aligned.m16n8k16.row.col.f32.f16.f16.f32 "
        "{%0,%1,%2,%3},{%4,%5,%6,%7},{%8,%9},{%0,%1,%2,%3};"
        : "+f"(c[0]), "+f"(c[1]), "+f"(c[2]), "+f"(c[3])
        : "r"(a[0]), "r"(a[1]), "r"(a[2]), "r"(a[3]), "r"(b[0]), "r"(b[1]));
}
__device__ __forceinline__ uint32_t f2h2(float a, float b) {
    __half2 h = __floats2half2_rn(a, b);
    return *reinterpret_cast<uint32_t*>(&h);
}

// ---------------------------------------------------------------------------
// zero the output (atomic-accumulated by gemm; graph-replay safe)
// ---------------------------------------------------------------------------
__global__ void __launch_bounds__(256) zero_kernel(float* __restrict__ out) {
    ((float4*)out)[blockIdx.x * 256 + threadIdx.x] = make_float4(0.f, 0.f, 0.f, 0.f);
}

// ---------------------------------------------------------------------------
// coeff transpose: coeff[o,i,k] f32 -> g_C[k][o][i] f16
// ---------------------------------------------------------------------------
__global__ void __launch_bounds__(256) ctrans_kernel(const float* __restrict__ coeff) {
    const int k = blockIdx.x;
    for (int idx = threadIdx.x; idx < 4096; idx += 256)
        g_C[k * 4096 + idx] = __float2half_rn(coeff[(size_t)idx * 64 + k]);
}

// ---------------------------------------------------------------------------
// W transpose + fp16: W[(k,e)][d] f32 -> g_B[d][(k,e)] f16
// ---------------------------------------------------------------------------
__global__ void __launch_bounds__(256) wsplit_kernel(const float* __restrict__ W) {
    __shared__ float s[32][33];
    const int kb = blockIdx.x;
    const int nb = blockIdx.y;
    const int tx = threadIdx.x & 31, tg = threadIdx.x >> 5;

#pragma unroll
    for (int r = 0; r < 4; ++r) {
        int kr = tg + r * 8;
        s[kr][tx] = W[(size_t)(kb * 32 + kr) * DD + nb * 32 + tx];
    }
    __syncthreads();
#pragma unroll
    for (int r = 0; r < 4; ++r) {
        int nr = tg + r * 8;
        g_B[(size_t)(nb * 32 + nr) * KTOT + kb * 32 + tx] = __float2half_rn(s[tx][nr]);
    }
}

// ---------------------------------------------------------------------------
// Stage 1 (tensorized): T[b*64+o][k*512+e] = sum_i coeff[o,i,k]*x[b,i,e]
// Output stored as MMA a-fragment blocks (proven in R12): STG.128 per
// (m16, k16) block -> perfectly coalesced 512B warp stores.
// ---------------------------------------------------------------------------
__global__ void __launch_bounds__(256, 1) stage1_mma_kernel(const float* __restrict__ x) {
    extern __shared__ char smem[];
    const uint32_t sb  = smem_u32(smem);
    const uint32_t sxb = sb;
    const uint32_t scb = sb + 65536;
    const int tid = threadIdx.x, lane = tid & 31, wid = tid >> 5;
    const int k = blockIdx.x * 8 + wid;
    const int b = blockIdx.y;

    const float* xb = x + (size_t)b * 64 * 512;
#pragma unroll 4
    for (int n = 0; n < 32; ++n) {
        int g = n * 256 + tid;
        int i = g >> 7, e = (g & 127) * 4;
        float4 v = *(const float4*)&xb[i * 512 + e];
        __half h[4] = {__float2half_rn(v.x), __float2half_rn(v.y),
                       __float2half_rn(v.z), __float2half_rn(v.w)};
#pragma unroll
        for (int j = 0; j < 4; ++j) {
            uint32_t off = (e + j) * 128 + ((i * 2) ^ (((e + j) & 7) * 16));
            *(__half*)(smem + off) = h[j];
        }
    }
    {
        const __half* gc = g_C + (size_t)k * 4096;
#pragma unroll
        for (int n = 0; n < 16; ++n) {
            int idx = n * 32 + lane;
            int o = idx >> 3, c8 = idx & 7;
            uint32_t off = 65536 + wid * 8192 + o * 128 + ((c8 * 16) ^ ((o & 7) * 16));
            *(int4*)(smem + off) = *(const int4*)(gc + o * 64 + c8 * 8);
        }
    }
    __syncthreads();

    const int a_row  = (lane & 7) | (((lane >> 3) & 1) << 3);
    const int a_k16b = (lane >> 4) * 16;
    const int b_nr   = (lane & 7) | (((lane >> 4) & 1) << 3);
    const int b_k16b = ((lane >> 3) & 1) * 16;

    uint32_t a[4][4][4];
#pragma unroll
    for (int ot = 0; ot < 4; ++ot)
#pragma unroll
        for (int k16 = 0; k16 < 4; ++k16) {
            int r = ot * 16 + a_row;
            uint32_t off = scb + wid * 8192 + r * 128 + ((k16 * 32 + a_k16b) ^ ((r & 7) * 16));
            ldsm4(a[ot][k16], off);
        }

    uint4* aOut = (uint4*)g_A;

#pragma unroll 1
    for (int et = 0; et < 16; ++et) {
        float acc[4][4][4];
#pragma unroll
        for (int ot = 0; ot < 4; ++ot)
#pragma unroll
            for (int nt = 0; nt < 4; ++nt)
#pragma unroll
                for (int j = 0; j < 4; ++j) acc[ot][nt][j] = 0.0f;

#pragma unroll
        for (int k16 = 0; k16 < 4; ++k16) {
            uint32_t bb[2][4];
#pragma unroll
            for (int p = 0; p < 2; ++p) {
                int nrow = et * 32 + p * 16 + b_nr;
                uint32_t off = sxb + nrow * 128 + ((k16 * 32 + b_k16b) ^ ((nrow & 7) * 16));
                ldsm4(bb[p], off);
            }
#pragma unroll
            for (int ot = 0; ot < 4; ++ot)
#pragma unroll
                for (int nt = 0; nt < 4; ++nt)
                    mma_f16(acc[ot][nt], a[ot][k16], &bb[nt >> 1][(nt & 1) * 2]);
        }

        // store as a-frag blocks: (m16 tile = b*4+ot, k16 tile = k*32+et*2+ntp)
#pragma unroll
        for (int ot = 0; ot < 4; ++ot) {
            const size_t mt = (size_t)(b * 4 + ot);
#pragma unroll
            for (int ntp = 0; ntp < 2; ++ntp) {
                uint4 v;
                v.x = f2h2(acc[ot][2 * ntp][0],     acc[ot][2 * ntp][1]);
                v.y = f2h2(acc[ot][2 * ntp][2],     acc[ot][2 * ntp][3]);
                v.z = f2h2(acc[ot][2 * ntp + 1][0], acc[ot][2 * ntp + 1][1]);
                v.w = f2h2(acc[ot][2 * ntp + 1][2], acc[ot][2 * ntp + 1][3]);
                size_t kt = (size_t)k * 32 + et * 2 + ntp;
                aOut[(mt * 2048 + kt) * 32 + lane] = v;
            }
        }
    }
}

// ---------------------------------------------------------------------------
// Stage 2: fp16 split-K GEMM (R9 geometry + frag-block A + atomic epilogue).
//  A: cp.async of frag blocks (linear, no swizzle) + LDS.128 (conflict-free).
//  B: cp.async SW128 + ldmatrix (R9-proven).
//  CTA 64x128, 8 warps (warp 32x32, 2m x 4n), 3 CTAs/SM, grid (4,32,16)=2048.
//  Epilogue: RED.ADD into out (zeroed at graph start).
// ---------------------------------------------------------------------------
__global__ void __launch_bounds__(256, 3) gemm_kernel(float* __restrict__ out) {
    extern __shared__ char smem[];
    const uint32_t sb = (smem_u32(smem) + 1023) & ~1023u;

    const int tid  = threadIdx.x;
    const int lane = tid & 31;
    const int wid  = tid >> 5;
    const int n0 = blockIdx.x * BN;
    const int m0 = blockIdx.y * BM;
    const size_t k0 = (size_t)blockIdx.z * KPER;
    const int warp_m = (wid & 1) * 32;
    const int warp_n = (wid >> 1) * 32;

    // ---- A cp.async: frag blocks, 8 KB/chunk. thread: mtq (0..3), rq (0..63);
    //      loads 16B units rq and rq+64 of the 2KB (4 contiguous kt blocks) region.
    const int mtq = tid >> 6;
    const int rq  = tid & 63;
    const size_t mtile0 = (size_t)(m0 >> 4);
    const size_t kt0 = k0 >> 4;
    const uint4* gAblk = (const uint4*)g_A + ((mtile0 + mtq) * 2048 + kt0) * 32;
    const int ktl0 = rq >> 5, w0 = rq & 31;
    const uint32_t aoff0 = (uint32_t)((ktl0 * 4 + mtq) * 512 + w0 * 16);
    const uint32_t aoff1 = (uint32_t)(((ktl0 + 2) * 4 + mtq) * 512 + w0 * 16);

    // ---- B cp.async: 128 rows x 128 B per stage (2 thr/row, 4x16B each) ----
    const int rB = tid >> 1, cB = (tid & 1) * 4;
    const __half* gB = g_B + (size_t)(n0 + rB) * KTOT + k0 + cB * 8;
    uint32_t swzB[4];
#pragma unroll
    for (int j = 0; j < 4; ++j)
        swzB[j] = 8192 + rB * 128 + (((cB + j) * 16) ^ ((rB & 7) * 16));

    const int b_nr   = (lane & 7) | (((lane >> 4) & 1) << 3);
    const int b_k16b = ((lane >> 3) & 1) * 16;
    const int mtb    = warp_m >> 4;   // 0 or 2

    float acc[2][4][4];
#pragma unroll
    for (int mt = 0; mt < 2; ++mt)
#pragma unroll
        for (int nt = 0; nt < 4; ++nt)
#pragma unroll
            for (int j = 0; j < 4; ++j) acc[mt][nt][j] = 0.0f;

    auto load_stage = [&](int c, int s) {
        const uint32_t base = sb + s * STAGE_BYTES;
        // A: 2 units from contiguous frag-block region
        const uint4* src = gAblk + (size_t)c * 128;
        cp16(base + aoff0, src + rq);
        cp16(base + aoff1, src + rq + 64);
        // B
        const int ke = c * BK;
#pragma unroll
        for (int j = 0; j < 4; ++j)
            cp16(base + swzB[j], gB + ke + j * 8);
        CP_COMMIT();
    };

    load_stage(0, 0);
    load_stage(1, 1);

    int s = 0;
    for (int c = 0; c < NCH; ++c) {
        if (c + 1 < NCH) { CP_WAIT(1); } else { CP_WAIT(0); }
        __syncthreads();
        if (c + 2 < NCH) load_stage(c + 2, (c + 2) % NSTG);

        const uint32_t Ab = sb + s * STAGE_BYTES;
        const uint32_t Bb = Ab;   // B at +8192 handled in offsets below

#pragma unroll
        for (int k16 = 0; k16 < 4; ++k16) {
            uint32_t a[2][4], bb[2][4];
#pragma unroll
            for (int mt = 0; mt < 2; ++mt)
                lds128(a[mt], Ab + (uint32_t)((k16 * 4 + mtb + mt) * 512 + lane * 16));
#pragma unroll
            for (int p = 0; p < 2; ++p) {
                int n = warp_n + p * 16 + b_nr;
                ldsm4(bb[p], Bb + 8192 + n * 128 + ((k16 * 32 + b_k16b) ^ ((n & 7) * 16)));
            }
#pragma unroll
            for (int mt = 0; mt < 2; ++mt)
#pragma unroll
                for (int nt = 0; nt < 4; ++nt)
                    mma_f16(acc[mt][nt], a[mt], &bb[nt >> 1][(nt & 1) * 2]);
        }
        s = (s + 1 == NSTG) ? 0 : s + 1;
    }

    // ---- epilogue: RED.ADD into out ----
#pragma unroll
    for (int mt = 0; mt < 2; ++mt)
#pragma unroll
        for (int nt = 0; nt < 4; ++nt) {
            int r    = m0 + warp_m + mt * 16 + (lane >> 2);
            int ccol = n0 + warp_n + nt * 8 + (lane & 3) * 2;
            float* p0 = &out[(size_t)r * DD + ccol];
            float* p1 = &out[(size_t)(r + 8) * DD + ccol];
            atomicAdd(p0,     acc[mt][nt][0]);
            atomicAdd(p0 + 1, acc[mt][nt][1]);
            atomicAdd(p1,     acc[mt][nt][2]);
            atomicAdd(p1 + 1, acc[mt][nt][3]);
        }
}

extern "C" void kernel_launch(void* const* d_in, const int* in_sizes, int n_in,
                              void* d_out, int out_size) {
    const float* x     = (const float*)d_in[0];  // [32,64,512]
    const float* w     = (const float*)d_in[1];  // [64,512,512]
    const float* coeff = (const float*)d_in[2];  // [64,64,64]
    float* out = (float*)d_out;                  // [32,64,512]

    cudaFuncSetAttribute(gemm_kernel,       cudaFuncAttributeMaxDynamicSharedMemorySize, GEMM_SMEM);
    cudaFuncSetAttribute(stage1_mma_kernel, cudaFuncAttributeMaxDynamicSharedMemorySize, S1_SMEM);

    zero_kernel<<<(MM * DD / 4) / 256, 256>>>(out);
    ctrans_kernel<<<KK, 256>>>(coeff);
    wsplit_kernel<<<dim3(KTOT / 32, DD / 32), 256>>>(w);
    stage1_mma_kernel<<<dim3(KK / 8, B_), 256, S1_SMEM>>>(x);
    gemm_kernel<<<dim3(DD / BN, MM / BM, SPLIT), 256, GEMM_SMEM>>>(out);
}

// round 14
// speedup vs baseline: 1.5140x; 1.0212x over previous
#include <cuda_runtime.h>
#include <cuda_fp16.h>
#include <cstdint>

// ---------------- problem constants ----------------
#define B_    32
#define DD    512
#define KK    64
#define KTOT  32768            // K*D : flattened reduction dim
#define MM    2048             // B*F_out
#define SPLIT 16
#define KPER  (KTOT / SPLIT)   // 2048
#define BK    64               // k elems per chunk
#define NCH   (KPER / BK)      // 32
#define BM    64
#define BN    128
#define NSTG  3
#define STAGE_BYTES 24576      // A frag-blocks 8K + B 16K
#define GEMM_SMEM   (NSTG * STAGE_BYTES + 1024)
#define S1_SMEM     131072     // sX 64K + sC 64K
#define XP_SMEM     65536

// ---------------- device scratch (no allocation) ----------------
// g_A: MMA-fragment-block layout. Block (m16-tile mt, k16-tile kt):
//   uint4 index (mt*2048 + kt)*32 + lane.
__device__ __half g_A[(size_t)MM * KTOT];          // 128 MB
__device__ __half g_B[(size_t)DD * KTOT];          // 32 MB  (W^T fp16, [d][k,e])
__device__ __half g_Cs[(size_t)KK * 4096];         // 512 KB (coeff swizzled ldsm blocks)
__device__ __half g_X[(size_t)B_ * 64 * 512];      // 2 MB   (x fp16, swizzled smem image per b)

// ---------------- helpers ----------------
__device__ __forceinline__ uint32_t smem_u32(const void* p) {
    uint32_t a;
    asm("{ .reg .u64 t; cvta.to.shared.u64 t, %1; cvt.u32.u64 %0, t; }" : "=r"(a) : "l"(p));
    return a;
}
__device__ __forceinline__ void cp16(uint32_t dst, const void* src) {
    asm volatile("cp.async.cg.shared.global [%0], [%1], 16;" :: "r"(dst), "l"(src));
}
#define CP_COMMIT() asm volatile("cp.async.commit_group;" ::: "memory")
#define CP_WAIT(n)  asm volatile("cp.async.wait_group %0;" :: "n"(n) : "memory")

__device__ __forceinline__ void ldsm4(uint32_t* r, uint32_t addr) {
    asm volatile("ldmatrix.sync.aligned.m8n8.x4.shared.b16 {%0,%1,%2,%3}, [%4];"
                 : "=r"(r[0]), "=r"(r[1]), "=r"(r[2]), "=r"(r[3]) : "r"(addr));
}
__device__ __forceinline__ void lds128(uint32_t* r, uint32_t addr) {
    asm volatile("ld.shared.v4.u32 {%0,%1,%2,%3}, [%4];"
                 : "=r"(r[0]), "=r"(r[1]), "=r"(r[2]), "=r"(r[3]) : "r"(addr));
}
__device__ __forceinline__ void mma_f16(float* c, const uint32_t* a, const uint32_t* b) {
    asm volatile(
        "mma.sync.aligned.m16n8k16.row.col.f32.f16.f16.f32 "
        "{%0,%1,%2,%3},{%4,%5,%6,%7},{%8,%9},{%0,%1,%2,%3};"
        : "+f"(c[0]), "+f"(c[1]), "+f"(c[2]), "+f"(c[3])
        : "r"(a[0]), "r"(a[1]), "r"(a[2]), "r"(a[3]), "r"(b[0]), "r"(b[1]));
}
__device__ __forceinline__ uint32_t f2h2(float a, float b) {
    __half2 h = __floats2half2_rn(a, b);
    return *reinterpret_cast<uint32_t*>(&h);
}

// ---------------------------------------------------------------------------
// zero the output (atomic-accumulated by gemm; graph-replay safe)
// ---------------------------------------------------------------------------
__global__ void __launch_bounds__(256) zero_kernel(float* __restrict__ out) {
    ((float4*)out)[blockIdx.x * 256 + threadIdx.x] = make_float4(0.f, 0.f, 0.f, 0.f);
}

// ---------------------------------------------------------------------------
// ctrans: coeff[o,i,k] f32 -> g_Cs[k] = swizzled ldsm-ready 8KB block [o][i]
// (byte offset within block: o*128 + ((i>>3)*16 ^ ((o&7)*16)) + (i&7)*2)
// ---------------------------------------------------------------------------
__global__ void __launch_bounds__(256) ctrans_kernel(const float* __restrict__ coeff) {
    const int k = blockIdx.x;
    char* dstb = (char*)g_Cs + (size_t)k * 8192;
    for (int idx = threadIdx.x; idx < 4096; idx += 256) {
        int o = idx >> 6, i = idx & 63;
        float v = coeff[(size_t)(o * 64 + i) * 64 + k];
        uint32_t off = o * 128 + (((i >> 3) * 16) ^ ((o & 7) * 16)) + (i & 7) * 2;
        *(__half*)(dstb + off) = __float2half_rn(v);
    }
}

// ---------------------------------------------------------------------------
// xprep: x[b] f32 [i][e] -> g_X[b] = swizzled fp16 smem image [e-row(128B)][i]
// ---------------------------------------------------------------------------
__global__ void __launch_bounds__(256) xprep_kernel(const float* __restrict__ x) {
    extern __shared__ char sx[];
    const int b = blockIdx.x, tid = threadIdx.x;
    const float* xb = x + (size_t)b * 64 * 512;
#pragma unroll 4
    for (int n = 0; n < 32; ++n) {
        int g = n * 256 + tid;
        int i = g >> 7, e = (g & 127) * 4;
        float4 v = *(const float4*)&xb[i * 512 + e];
        __half h[4] = {__float2half_rn(v.x), __float2half_rn(v.y),
                       __float2half_rn(v.z), __float2half_rn(v.w)};
#pragma unroll
        for (int j = 0; j < 4; ++j) {
            uint32_t off = (e + j) * 128 + ((i * 2) ^ (((e + j) & 7) * 16));
            *(__half*)(sx + off) = h[j];
        }
    }
    __syncthreads();
    int4* dst = (int4*)g_X + (size_t)b * 4096;
    const int4* src = (const int4*)sx;
#pragma unroll
    for (int j = 0; j < 16; ++j)
        dst[j * 256 + tid] = src[j * 256 + tid];
}

// ---------------------------------------------------------------------------
// wsplit: W[(k,e)][d] f32 -> g_B[d][(k,e)] f16, full-128B writes (64k x 32d tiles)
// ---------------------------------------------------------------------------
__global__ void __launch_bounds__(256) wsplit_kernel(const float* __restrict__ W) {
    __shared__ float s[64][33];
    const int kb = blockIdx.x;      // k-flat / 64
    const int nb = blockIdx.y;      // d / 32
    const int tx = threadIdx.x & 31, tg = threadIdx.x >> 5;

#pragma unroll
    for (int r = 0; r < 8; ++r) {
        int kr = tg * 8 + r;
        s[kr][tx] = W[(size_t)(kb * 64 + kr) * DD + nb * 32 + tx];
    }
    __syncthreads();
#pragma unroll
    for (int r = 0; r < 4; ++r) {
        int nr = tg * 4 + r;
        __half2 h = __floats2half2_rn(s[tx * 2][nr], s[tx * 2 + 1][nr]);
        *(__half2*)&g_B[(size_t)(nb * 32 + nr) * KTOT + kb * 64 + tx * 2] = h;
    }
}

// ---------------------------------------------------------------------------
// Stage 1 (tensorized, lean): cp.async prebuilt sX/sC images, MMA, frag-block stores.
// ---------------------------------------------------------------------------
__global__ void __launch_bounds__(256, 1) stage1_mma_kernel() {
    extern __shared__ char smem[];
    const uint32_t sb  = smem_u32(smem);
    const uint32_t sxb = sb;
    const uint32_t scb = sb + 65536;
    const int tid = threadIdx.x, lane = tid & 31, wid = tid >> 5;
    const int k = blockIdx.x * 8 + wid;
    const int b = blockIdx.y;

    // cp.async sX (64KB verbatim) + sC (8KB per warp verbatim)
    {
        const int4* gx = (const int4*)g_X + (size_t)b * 4096;
#pragma unroll
        for (int j = 0; j < 16; ++j)
            cp16(sxb + (j * 256 + tid) * 16, gx + j * 256 + tid);
        const int4* gc = (const int4*)g_Cs + (size_t)k * 512;
#pragma unroll
        for (int j = 0; j < 16; ++j)
            cp16(scb + wid * 8192 + (j * 32 + lane) * 16, gc + j * 32 + lane);
        CP_COMMIT();
        CP_WAIT(0);
    }
    __syncthreads();

    const int a_row  = (lane & 7) | (((lane >> 3) & 1) << 3);
    const int a_k16b = (lane >> 4) * 16;
    const int b_nr   = (lane & 7) | (((lane >> 4) & 1) << 3);
    const int b_k16b = ((lane >> 3) & 1) * 16;

    uint32_t a[4][4][4];
#pragma unroll
    for (int ot = 0; ot < 4; ++ot)
#pragma unroll
        for (int k16 = 0; k16 < 4; ++k16) {
            int r = ot * 16 + a_row;
            uint32_t off = scb + wid * 8192 + r * 128 + ((k16 * 32 + a_k16b) ^ ((r & 7) * 16));
            ldsm4(a[ot][k16], off);
        }

    uint4* aOut = (uint4*)g_A;

#pragma unroll 1
    for (int et = 0; et < 16; ++et) {
        float acc[4][4][4];
#pragma unroll
        for (int ot = 0; ot < 4; ++ot)
#pragma unroll
            for (int nt = 0; nt < 4; ++nt)
#pragma unroll
                for (int j = 0; j < 4; ++j) acc[ot][nt][j] = 0.0f;

#pragma unroll
        for (int k16 = 0; k16 < 4; ++k16) {
            uint32_t bb[2][4];
#pragma unroll
            for (int p = 0; p < 2; ++p) {
                int nrow = et * 32 + p * 16 + b_nr;
                uint32_t off = sxb + nrow * 128 + ((k16 * 32 + b_k16b) ^ ((nrow & 7) * 16));
                ldsm4(bb[p], off);
            }
#pragma unroll
            for (int ot = 0; ot < 4; ++ot)
#pragma unroll
                for (int nt = 0; nt < 4; ++nt)
                    mma_f16(acc[ot][nt], a[ot][k16], &bb[nt >> 1][(nt & 1) * 2]);
        }

#pragma unroll
        for (int ot = 0; ot < 4; ++ot) {
            const size_t mt = (size_t)(b * 4 + ot);
#pragma unroll
            for (int ntp = 0; ntp < 2; ++ntp) {
                uint4 v;
                v.x = f2h2(acc[ot][2 * ntp][0],     acc[ot][2 * ntp][1]);
                v.y = f2h2(acc[ot][2 * ntp][2],     acc[ot][2 * ntp][3]);
                v.z = f2h2(acc[ot][2 * ntp + 1][0], acc[ot][2 * ntp + 1][1]);
                v.w = f2h2(acc[ot][2 * ntp + 1][2], acc[ot][2 * ntp + 1][3]);
                size_t kt = (size_t)k * 32 + et * 2 + ntp;
                aOut[(mt * 2048 + kt) * 32 + lane] = v;
            }
        }
    }
}

// ---------------------------------------------------------------------------
// Stage 2: fp16 split-K GEMM (R13, unchanged — proven).
// ---------------------------------------------------------------------------
__global__ void __launch_bounds__(256, 3) gemm_kernel(float* __restrict__ out) {
    extern __shared__ char smem[];
    const uint32_t sb = (smem_u32(smem) + 1023) & ~1023u;

    const int tid  = threadIdx.x;
    const int lane = tid & 31;
    const int wid  = tid >> 5;
    const int n0 = blockIdx.x * BN;
    const int m0 = blockIdx.y * BM;
    const size_t k0 = (size_t)blockIdx.z * KPER;
    const int warp_m = (wid & 1) * 32;
    const int warp_n = (wid >> 1) * 32;

    const int mtq = tid >> 6;
    const int rq  = tid & 63;
    const size_t mtile0 = (size_t)(m0 >> 4);
    const size_t kt0 = k0 >> 4;
    const uint4* gAblk = (const uint4*)g_A + ((mtile0 + mtq) * 2048 + kt0) * 32;
    const int ktl0 = rq >> 5, w0 = rq & 31;
    const uint32_t aoff0 = (uint32_t)((ktl0 * 4 + mtq) * 512 + w0 * 16);
    const uint32_t aoff1 = (uint32_t)(((ktl0 + 2) * 4 + mtq) * 512 + w0 * 16);

    const int rB = tid >> 1, cB = (tid & 1) * 4;
    const __half* gB = g_B + (size_t)(n0 + rB) * KTOT + k0 + cB * 8;
    uint32_t swzB[4];
#pragma unroll
    for (int j = 0; j < 4; ++j)
        swzB[j] = 8192 + rB * 128 + (((cB + j) * 16) ^ ((rB & 7) * 16));

    const int b_nr   = (lane & 7) | (((lane >> 4) & 1) << 3);
    const int b_k16b = ((lane >> 3) & 1) * 16;
    const int mtb    = warp_m >> 4;

    float acc[2][4][4];
#pragma unroll
    for (int mt = 0; mt < 2; ++mt)
#pragma unroll
        for (int nt = 0; nt < 4; ++nt)
#pragma unroll
            for (int j = 0; j < 4; ++j) acc[mt][nt][j] = 0.0f;

    auto load_stage = [&](int c, int s) {
        const uint32_t base = sb + s * STAGE_BYTES;
        const uint4* src = gAblk + (size_t)c * 128;
        cp16(base + aoff0, src + rq);
        cp16(base + aoff1, src + rq + 64);
        const int ke = c * BK;
#pragma unroll
        for (int j = 0; j < 4; ++j)
            cp16(base + swzB[j], gB + ke + j * 8);
        CP_COMMIT();
    };

    load_stage(0, 0);
    load_stage(1, 1);

    int s = 0;
    for (int c = 0; c < NCH; ++c) {
        if (c + 1 < NCH) { CP_WAIT(1); } else { CP_WAIT(0); }
        __syncthreads();
        if (c + 2 < NCH) load_stage(c + 2, (c + 2) % NSTG);

        const uint32_t Ab = sb + s * STAGE_BYTES;

#pragma unroll
        for (int k16 = 0; k16 < 4; ++k16) {
            uint32_t a[2][4], bb[2][4];
#pragma unroll
            for (int mt = 0; mt < 2; ++mt)
                lds128(a[mt], Ab + (uint32_t)((k16 * 4 + mtb + mt) * 512 + lane * 16));
#pragma unroll
            for (int p = 0; p < 2; ++p) {
                int n = warp_n + p * 16 + b_nr;
                ldsm4(bb[p], Ab + 8192 + n * 128 + ((k16 * 32 + b_k16b) ^ ((n & 7) * 16)));
            }
#pragma unroll
            for (int mt = 0; mt < 2; ++mt)
#pragma unroll
                for (int nt = 0; nt < 4; ++nt)
                    mma_f16(acc[mt][nt], a[mt], &bb[nt >> 1][(nt & 1) * 2]);
        }
        s = (s + 1 == NSTG) ? 0 : s + 1;
    }

#pragma unroll
    for (int mt = 0; mt < 2; ++mt)
#pragma unroll
        for (int nt = 0; nt < 4; ++nt) {
            int r    = m0 + warp_m + mt * 16 + (lane >> 2);
            int ccol = n0 + warp_n + nt * 8 + (lane & 3) * 2;
            float* p0 = &out[(size_t)r * DD + ccol];
            float* p1 = &out[(size_t)(r + 8) * DD + ccol];
            atomicAdd(p0,     acc[mt][nt][0]);
            atomicAdd(p0 + 1, acc[mt][nt][1]);
            atomicAdd(p1,     acc[mt][nt][2]);
            atomicAdd(p1 + 1, acc[mt][nt][3]);
        }
}

extern "C" void kernel_launch(void* const* d_in, const int* in_sizes, int n_in,
                              void* d_out, int out_size) {
    const float* x     = (const float*)d_in[0];  // [32,64,512]
    const float* w     = (const float*)d_in[1];  // [64,512,512]
    const float* coeff = (const float*)d_in[2];  // [64,64,64]
    float* out = (float*)d_out;                  // [32,64,512]

    cudaFuncSetAttribute(gemm_kernel,       cudaFuncAttributeMaxDynamicSharedMemorySize, GEMM_SMEM);
    cudaFuncSetAttribute(stage1_mma_kernel, cudaFuncAttributeMaxDynamicSharedMemorySize, S1_SMEM);
    cudaFuncSetAttribute(xprep_kernel,      cudaFuncAttributeMaxDynamicSharedMemorySize, XP_SMEM);

    zero_kernel<<<(MM * DD / 4) / 256, 256>>>(out);
    ctrans_kernel<<<KK, 256>>>(coeff);
    xprep_kernel<<<B_, 256, XP_SMEM>>>(x);
    wsplit_kernel<<<dim3(KTOT / 64, DD / 32), 256>>>(w);
    stage1_mma_kernel<<<dim3(KK / 8, B_), 256, S1_SMEM>>>();
    gemm_kernel<<<dim3(DD / BN, MM / BM, SPLIT), 256, GEMM_SMEM>>>(out);
}

// round 15
// speedup vs baseline: 1.5252x; 1.0074x over previous
#include <cuda_runtime.h>
#include <cuda_fp16.h>
#include <cstdint>

// ---------------- problem constants ----------------
#define B_    32
#define DD    512
#define KK    64
#define KTOT  32768            // K*D : flattened reduction dim
#define MM    2048             // B*F_out
#define SPLIT 16
#define KPER  (KTOT / SPLIT)   // 2048
#define BK    64               // k elems per chunk
#define NCH   (KPER / BK)      // 32
#define BM    64
#define BN    128
#define NSTG  3
#define STAGE_BYTES 24576      // A frag-blocks 8K + B 16K
#define GEMM_SMEM   (NSTG * STAGE_BYTES + 1024)
#define P1_SMEM     65536      // xprep image build
#define P2_SMEM     46080      // sC 32K + 3 x 4K sX slices (+pad)

// ---------------- device scratch (no allocation) ----------------
// g_A: MMA-fragment-block layout. Block (m16-tile mt, k16-tile kt):
//   uint4 index (mt*2048 + kt)*32 + lane.
__device__ __half g_A[(size_t)MM * KTOT];          // 128 MB
__device__ __half g_B[(size_t)DD * KTOT];          // 32 MB  (W^T fp16, [d][k,e])
__device__ __half g_Cs[(size_t)KK * 4096];         // 512 KB (coeff swizzled ldsm blocks)
__device__ __half g_X[(size_t)B_ * 64 * 512];      // 2 MB   (x fp16, swizzled smem image per b)

// ---------------- helpers ----------------
__device__ __forceinline__ uint32_t smem_u32(const void* p) {
    uint32_t a;
    asm("{ .reg .u64 t; cvta.to.shared.u64 t, %1; cvt.u32.u64 %0, t; }" : "=r"(a) : "l"(p));
    return a;
}
__device__ __forceinline__ void cp16(uint32_t dst, const void* src) {
    asm volatile("cp.async.cg.shared.global [%0], [%1], 16;" :: "r"(dst), "l"(src));
}
#define CP_COMMIT() asm volatile("cp.async.commit_group;" ::: "memory")
#define CP_WAIT(n)  asm volatile("cp.async.wait_group %0;" :: "n"(n) : "memory")

__device__ __forceinline__ void ldsm4(uint32_t* r, uint32_t addr) {
    asm volatile("ldmatrix.sync.aligned.m8n8.x4.shared.b16 {%0,%1,%2,%3}, [%4];"
                 : "=r"(r[0]), "=r"(r[1]), "=r"(r[2]), "=r"(r[3]) : "r"(addr));
}
__device__ __forceinline__ void lds128(uint32_t* r, uint32_t addr) {
    asm volatile("ld.shared.v4.u32 {%0,%1,%2,%3}, [%4];"
                 : "=r"(r[0]), "=r"(r[1]), "=r"(r[2]), "=r"(r[3]) : "r"(addr));
}
__device__ __forceinline__ void mma_f16(float* c, const uint32_t* a, const uint32_t* b) {
    asm volatile(
        "mma.sync.aligned.m16n8k16.row.col.f32.f16.f16.f32 "
        "{%0,%1,%2,%3},{%4,%5,%6,%7},{%8,%9},{%0,%1,%2,%3};"
        : "+f"(c[0]), "+f"(c[1]), "+f"(c[2]), "+f"(c[3])
        : "r"(a[0]), "r"(a[1]), "r"(a[2]), "r"(a[3]), "r"(b[0]), "r"(b[1]));
}
__device__ __forceinline__ uint32_t f2h2(float a, float b) {
    __half2 h = __floats2half2_rn(a, b);
    return *reinterpret_cast<uint32_t*>(&h);
}

// ---------------------------------------------------------------------------
// prep1: fused zero(out) + ctrans + xprep.  grid 608, 256 thr, 64KB dyn smem.
//  blk [0,32): xprep(b=blk)  [32,96): ctrans(k=blk-32)  [96,608): zero
// ---------------------------------------------------------------------------
__global__ void __launch_bounds__(256) prep1_kernel(const float* __restrict__ x,
                                                    const float* __restrict__ coeff,
                                                    float* __restrict__ out) {
    extern __shared__ char sx[];
    const int blk = blockIdx.x, tid = threadIdx.x;

    if (blk < 32) {
        // ---- xprep: x[b] f32 -> swizzled fp16 smem image in g_X ----
        const int b = blk;
        const float* xb = x + (size_t)b * 64 * 512;
#pragma unroll 4
        for (int n = 0; n < 32; ++n) {
            int g = n * 256 + tid;
            int i = g >> 7, e = (g & 127) * 4;
            float4 v = *(const float4*)&xb[i * 512 + e];
            __half h[4] = {__float2half_rn(v.x), __float2half_rn(v.y),
                           __float2half_rn(v.z), __float2half_rn(v.w)};
#pragma unroll
            for (int j = 0; j < 4; ++j) {
                uint32_t off = (e + j) * 128 + ((i * 2) ^ (((e + j) & 7) * 16));
                *(__half*)(sx + off) = h[j];
            }
        }
        __syncthreads();
        int4* dst = (int4*)g_X + (size_t)b * 4096;
        const int4* src = (const int4*)sx;
#pragma unroll
        for (int j = 0; j < 16; ++j)
            dst[j * 256 + tid] = src[j * 256 + tid];
    } else if (blk < 96) {
        // ---- ctrans: coeff -> g_Cs[k] swizzled ldsm-ready block ----
        const int k = blk - 32;
        char* dstb = (char*)g_Cs + (size_t)k * 8192;
        for (int idx = tid; idx < 4096; idx += 256) {
            int o = idx >> 6, i = idx & 63;
            float v = coeff[(size_t)(o * 64 + i) * 64 + k];
            uint32_t off = o * 128 + (((i >> 3) * 16) ^ ((o & 7) * 16)) + (i & 7) * 2;
            *(__half*)(dstb + off) = __float2half_rn(v);
        }
    } else {
        // ---- zero out ----
        const int idx = blk - 96;
        float4* o4 = (float4*)out;
        o4[idx * 512 + tid]       = make_float4(0.f, 0.f, 0.f, 0.f);
        o4[idx * 512 + 256 + tid] = make_float4(0.f, 0.f, 0.f, 0.f);
    }
}

// ---------------------------------------------------------------------------
// prep2: fused stage1 (tensorized, sX slice pipeline) + wsplit, role-interleaved.
//  grid 2560, 128 thr, 45KB dyn smem, 3 CTAs/SM.
//  blk%5==0 -> stage1 role (sid=blk/5, 512 total): warp handles one k.
//  else     -> wsplit role (2048 total, 4 k-tiles each).
// ---------------------------------------------------------------------------
__global__ void __launch_bounds__(128, 3) prep2_kernel(const float* __restrict__ W) {
    extern __shared__ char smem[];
    const int blk = blockIdx.x, tid = threadIdx.x;
    const int lane = tid & 31, wid = tid >> 5;

    if (blk % 5 == 0) {
        // ================= stage1 role =================
        const int sid  = blk / 5;          // 0..511
        const int kgrp = sid & 15;
        const int b    = sid >> 4;
        const int k    = kgrp * 4 + wid;

        const uint32_t sb  = smem_u32(smem);
        const uint32_t scb = sb;           // 32 KB: sC per warp 8KB
        const uint32_t sxp = sb + 32768;   // 3 x 4KB sX slices

        // C0: sC (verbatim 8KB per warp) + slice 0 ; C1: slice 1
        const int4* gc = (const int4*)g_Cs + (size_t)k * 512;
#pragma unroll
        for (int j = 0; j < 16; ++j)
            cp16(scb + wid * 8192 + (j * 32 + lane) * 16, gc + j * 32 + lane);
        const int4* gx = (const int4*)g_X + (size_t)b * 4096;
        cp16(sxp + tid * 16,        gx + tid);
        cp16(sxp + 2048 + tid * 16, gx + 128 + tid);
        CP_COMMIT();
        cp16(sxp + 4096 + tid * 16,        gx + 256 + tid);
        cp16(sxp + 4096 + 2048 + tid * 16, gx + 256 + 128 + tid);
        CP_COMMIT();

        CP_WAIT(1);
        __syncthreads();

        const int a_row  = (lane & 7) | (((lane >> 3) & 1) << 3);
        const int a_k16b = (lane >> 4) * 16;
        const int b_nr   = (lane & 7) | (((lane >> 4) & 1) << 3);
        const int b_k16b = ((lane >> 3) & 1) * 16;

        // a-fragments (coeff_k) held in regs for the whole kernel
        uint32_t a[4][4][4];
#pragma unroll
        for (int ot = 0; ot < 4; ++ot)
#pragma unroll
            for (int k16 = 0; k16 < 4; ++k16) {
                int r = ot * 16 + a_row;
                uint32_t off = scb + wid * 8192 + r * 128 +
                               ((k16 * 32 + a_k16b) ^ ((r & 7) * 16));
                ldsm4(a[ot][k16], off);
            }

        uint4* aOut = (uint4*)g_A;

#pragma unroll 1
        for (int et = 0; et < 16; ++et) {
            if (et > 0) {
                if (et < 15) { CP_WAIT(1); } else { CP_WAIT(0); }
                __syncthreads();
            }
            if (et + 2 < 16) {
                const int st = (et + 2) % 3;
                cp16(sxp + st * 4096 + tid * 16,        gx + (et + 2) * 256 + tid);
                cp16(sxp + st * 4096 + 2048 + tid * 16, gx + (et + 2) * 256 + 128 + tid);
                CP_COMMIT();
            }
            const uint32_t sxs = sxp + (et % 3) * 4096;

            float acc[4][4][4];
#pragma unroll
            for (int ot = 0; ot < 4; ++ot)
#pragma unroll
                for (int nt = 0; nt < 4; ++nt)
#pragma unroll
                    for (int j = 0; j < 4; ++j) acc[ot][nt][j] = 0.0f;

#pragma unroll
            for (int k16 = 0; k16 < 4; ++k16) {
                uint32_t bb[2][4];
#pragma unroll
                for (int p = 0; p < 2; ++p) {
                    int lr = p * 16 + b_nr;
                    uint32_t off = sxs + lr * 128 +
                                   ((k16 * 32 + b_k16b) ^ ((lr & 7) * 16));
                    ldsm4(bb[p], off);
                }
#pragma unroll
                for (int ot = 0; ot < 4; ++ot)
#pragma unroll
                    for (int nt = 0; nt < 4; ++nt)
                        mma_f16(acc[ot][nt], a[ot][k16], &bb[nt >> 1][(nt & 1) * 2]);
            }

#pragma unroll
            for (int ot = 0; ot < 4; ++ot) {
                const size_t mt = (size_t)(b * 4 + ot);
#pragma unroll
                for (int ntp = 0; ntp < 2; ++ntp) {
                    uint4 v;
                    v.x = f2h2(acc[ot][2 * ntp][0],     acc[ot][2 * ntp][1]);
                    v.y = f2h2(acc[ot][2 * ntp][2],     acc[ot][2 * ntp][3]);
                    v.z = f2h2(acc[ot][2 * ntp + 1][0], acc[ot][2 * ntp + 1][1]);
                    v.w = f2h2(acc[ot][2 * ntp + 1][2], acc[ot][2 * ntp + 1][3]);
                    size_t kt = (size_t)k * 32 + et * 2 + ntp;
                    aOut[(mt * 2048 + kt) * 32 + lane] = v;
                }
            }
        }
    } else {
        // ================= wsplit role =================
        // idx 0..2047: nb = idx & 15, kb = (idx>>4)*4 + j  (4 tiles per block)
        const int q = blk / 5, r5 = blk % 5;
        const int idx = q * 4 + r5 - 1;
        const int nb = idx & 15;
        const int kb0 = (idx >> 4) * 4;

        float (*s)[33] = (float (*)[33])smem;
        const int tx = lane, tg = wid;   // 4 warps

#pragma unroll 1
        for (int j = 0; j < 4; ++j) {
            const int kb = kb0 + j;
#pragma unroll
            for (int r = 0; r < 16; ++r) {
                int kr = tg + r * 4;
                s[kr][tx] = W[(size_t)(kb * 64 + kr) * DD + nb * 32 + tx];
            }
            __syncthreads();
#pragma unroll
            for (int r = 0; r < 8; ++r) {
                int nr = tg * 8 + r;
                __half2 h = __floats2half2_rn(s[tx * 2][nr], s[tx * 2 + 1][nr]);
                *(__half2*)&g_B[(size_t)(nb * 32 + nr) * KTOT + kb * 64 + tx * 2] = h;
            }
            __syncthreads();
        }
    }
}

// ---------------------------------------------------------------------------
// Stage 2: fp16 split-K GEMM (R13/R14, unchanged — proven).
// ---------------------------------------------------------------------------
__global__ void __launch_bounds__(256, 3) gemm_kernel(float* __restrict__ out) {
    extern __shared__ char smem[];
    const uint32_t sb = (smem_u32(smem) + 1023) & ~1023u;

    const int tid  = threadIdx.x;
    const int lane = tid & 31;
    const int wid  = tid >> 5;
    const int n0 = blockIdx.x * BN;
    const int m0 = blockIdx.y * BM;
    const size_t k0 = (size_t)blockIdx.z * KPER;
    const int warp_m = (wid & 1) * 32;
    const int warp_n = (wid >> 1) * 32;

    const int mtq = tid >> 6;
    const int rq  = tid & 63;
    const size_t mtile0 = (size_t)(m0 >> 4);
    const size_t kt0 = k0 >> 4;
    const uint4* gAblk = (const uint4*)g_A + ((mtile0 + mtq) * 2048 + kt0) * 32;
    const int ktl0 = rq >> 5, w0 = rq & 31;
    const uint32_t aoff0 = (uint32_t)((ktl0 * 4 + mtq) * 512 + w0 * 16);
    const uint32_t aoff1 = (uint32_t)(((ktl0 + 2) * 4 + mtq) * 512 + w0 * 16);

    const int rB = tid >> 1, cB = (tid & 1) * 4;
    const __half* gB = g_B + (size_t)(n0 + rB) * KTOT + k0 + cB * 8;
    uint32_t swzB[4];
#pragma unroll
    for (int j = 0; j < 4; ++j)
        swzB[j] = 8192 + rB * 128 + (((cB + j) * 16) ^ ((rB & 7) * 16));

    const int b_nr   = (lane & 7) | (((lane >> 4) & 1) << 3);
    const int b_k16b = ((lane >> 3) & 1) * 16;
    const int mtb    = warp_m >> 4;

    float acc[2][4][4];
#pragma unroll
    for (int mt = 0; mt < 2; ++mt)
#pragma unroll
        for (int nt = 0; nt < 4; ++nt)
#pragma unroll
            for (int j = 0; j < 4; ++j) acc[mt][nt][j] = 0.0f;

    auto load_stage = [&](int c, int s) {
        const uint32_t base = sb + s * STAGE_BYTES;
        const uint4* src = gAblk + (size_t)c * 128;
        cp16(base + aoff0, src + rq);
        cp16(base + aoff1, src + rq + 64);
        const int ke = c * BK;
#pragma unroll
        for (int j = 0; j < 4; ++j)
            cp16(base + swzB[j], gB + ke + j * 8);
        CP_COMMIT();
    };

    load_stage(0, 0);
    load_stage(1, 1);

    int s = 0;
    for (int c = 0; c < NCH; ++c) {
        if (c + 1 < NCH) { CP_WAIT(1); } else { CP_WAIT(0); }
        __syncthreads();
        if (c + 2 < NCH) load_stage(c + 2, (c + 2) % NSTG);

        const uint32_t Ab = sb + s * STAGE_BYTES;

#pragma unroll
        for (int k16 = 0; k16 < 4; ++k16) {
            uint32_t a[2][4], bb[2][4];
#pragma unroll
            for (int mt = 0; mt < 2; ++mt)
                lds128(a[mt], Ab + (uint32_t)((k16 * 4 + mtb + mt) * 512 + lane * 16));
#pragma unroll
            for (int p = 0; p < 2; ++p) {
                int n = warp_n + p * 16 + b_nr;
                ldsm4(bb[p], Ab + 8192 + n * 128 + ((k16 * 32 + b_k16b) ^ ((n & 7) * 16)));
            }
#pragma unroll
            for (int mt = 0; mt < 2; ++mt)
#pragma unroll
                for (int nt = 0; nt < 4; ++nt)
                    mma_f16(acc[mt][nt], a[mt], &bb[nt >> 1][(nt & 1) * 2]);
        }
        s = (s + 1 == NSTG) ? 0 : s + 1;
    }

#pragma unroll
    for (int mt = 0; mt < 2; ++mt)
#pragma unroll
        for (int nt = 0; nt < 4; ++nt) {
            int r    = m0 + warp_m + mt * 16 + (lane >> 2);
            int ccol = n0 + warp_n + nt * 8 + (lane & 3) * 2;
            float* p0 = &out[(size_t)r * DD + ccol];
            float* p1 = &out[(size_t)(r + 8) * DD + ccol];
            atomicAdd(p0,     acc[mt][nt][0]);
            atomicAdd(p0 + 1, acc[mt][nt][1]);
            atomicAdd(p1,     acc[mt][nt][2]);
            atomicAdd(p1 + 1, acc[mt][nt][3]);
        }
}

extern "C" void kernel_launch(void* const* d_in, const int* in_sizes, int n_in,
                              void* d_out, int out_size) {
    const float* x     = (const float*)d_in[0];  // [32,64,512]
    const float* w     = (const float*)d_in[1];  // [64,512,512]
    const float* coeff = (const float*)d_in[2];  // [64,64,64]
    float* out = (float*)d_out;                  // [32,64,512]

    cudaFuncSetAttribute(gemm_kernel,  cudaFuncAttributeMaxDynamicSharedMemorySize, GEMM_SMEM);
    cudaFuncSetAttribute(prep1_kernel, cudaFuncAttributeMaxDynamicSharedMemorySize, P1_SMEM);
    cudaFuncSetAttribute(prep2_kernel, cudaFuncAttributeMaxDynamicSharedMemorySize, P2_SMEM);

    prep1_kernel<<<608, 256, P1_SMEM>>>(x, coeff, out);
    prep2_kernel<<<2560, 128, P2_SMEM>>>(w);
    gemm_kernel<<<dim3(DD / BN, MM / BM, SPLIT), 256, GEMM_SMEM>>>(out);
}

// round 16
// speedup vs baseline: 1.5336x; 1.0055x over previous
#include <cuda_runtime.h>
#include <cuda_fp16.h>
#include <cstdint>

// ---------------- problem constants ----------------
#define B_    32
#define DD    512
#define KK    64
#define KTOT  32768            // K*D : flattened reduction dim
#define MM    2048             // B*F_out
#define SPLIT 32
#define KPER  (KTOT / SPLIT)   // 1024
#define BK    64               // k elems per chunk
#define NCH   (KPER / BK)      // 16
#define BM    64
#define BN    128
#define NSTG  3
#define STAGE_BYTES 24576      // A frag-blocks 8K + B 16K
#define GEMM_SMEM   (NSTG * STAGE_BYTES + 1024)
#define P1_SMEM     16384      // xprep quarter-image build
#define P2_SMEM     46080      // sC 32K + 3 x 4K sX slices (+pad)

// ---------------- device scratch (no allocation) ----------------
// g_A: MMA-fragment-block layout. Block (m16-tile mt, k16-tile kt):
//   uint4 index (mt*2048 + kt)*32 + lane.
__device__ __half g_A[(size_t)MM * KTOT];          // 128 MB
__device__ __half g_B[(size_t)DD * KTOT];          // 32 MB  (W^T fp16, [d][k,e])
__device__ __half g_Cs[(size_t)KK * 4096];         // 512 KB (coeff swizzled ldsm blocks)
__device__ __half g_X[(size_t)B_ * 64 * 512];      // 2 MB   (x fp16, swizzled smem image per b)

// ---------------- helpers ----------------
__device__ __forceinline__ uint32_t smem_u32(const void* p) {
    uint32_t a;
    asm("{ .reg .u64 t; cvta.to.shared.u64 t, %1; cvt.u32.u64 %0, t; }" : "=r"(a) : "l"(p));
    return a;
}
__device__ __forceinline__ void cp16(uint32_t dst, const void* src) {
    asm volatile("cp.async.cg.shared.global [%0], [%1], 16;" :: "r"(dst), "l"(src));
}
#define CP_COMMIT() asm volatile("cp.async.commit_group;" ::: "memory")
#define CP_WAIT(n)  asm volatile("cp.async.wait_group %0;" :: "n"(n) : "memory")

__device__ __forceinline__ void ldsm4(uint32_t* r, uint32_t addr) {
    asm volatile("ldmatrix.sync.aligned.m8n8.x4.shared.b16 {%0,%1,%2,%3}, [%4];"
                 : "=r"(r[0]), "=r"(r[1]), "=r"(r[2]), "=r"(r[3]) : "r"(addr));
}
__device__ __forceinline__ void lds128(uint32_t* r, uint32_t addr) {
    asm volatile("ld.shared.v4.u32 {%0,%1,%2,%3}, [%4];"
                 : "=r"(r[0]), "=r"(r[1]), "=r"(r[2]), "=r"(r[3]) : "r"(addr));
}
__device__ __forceinline__ void mma_f16(float* c, const uint32_t* a, const uint32_t* b) {
    asm volatile(
        "mma.sync.aligned.m16n8k16.row.col.f32.f16.f16.f32 "
        "{%0,%1,%2,%3},{%4,%5,%6,%7},{%8,%9},{%0,%1,%2,%3};"
        : "+f"(c[0]), "+f"(c[1]), "+f"(c[2]), "+f"(c[3])
        : "r"(a[0]), "r"(a[1]), "r"(a[2]), "r"(a[3]), "r"(b[0]), "r"(b[1]));
}
__device__ __forceinline__ uint32_t f2h2(float a, float b) {
    __half2 h = __floats2half2_rn(a, b);
    return *reinterpret_cast<uint32_t*>(&h);
}

// ---------------------------------------------------------------------------
// prep1: fused zero(out) + ctrans + xprep(split 4x).  grid 704, 256 thr.
//  blk [0,128): xprep quarter (b=blk>>2, e0=(blk&3)*128)
//  blk [128,192): ctrans(k=blk-128)    blk [192,704): zero
// ---------------------------------------------------------------------------
__global__ void __launch_bounds__(256) prep1_kernel(const float* __restrict__ x,
                                                    const float* __restrict__ coeff,
                                                    float* __restrict__ out) {
    extern __shared__ char sx[];
    const int blk = blockIdx.x, tid = threadIdx.x;

    if (blk < 128) {
        // ---- xprep quarter: 128 e-rows of the swizzled fp16 image ----
        const int b  = blk >> 2;
        const int e0 = (blk & 3) * 128;
        const float* xb = x + (size_t)b * 64 * 512 + e0;
#pragma unroll 2
        for (int n = 0; n < 8; ++n) {
            int g = n * 256 + tid;           // 2048 float4 total
            int i = g >> 5, e = (g & 31) * 4;  // e local 0..127
            float4 v = *(const float4*)&xb[i * 512 + e];
            __half h[4] = {__float2half_rn(v.x), __float2half_rn(v.y),
                           __float2half_rn(v.z), __float2half_rn(v.w)};
#pragma unroll
            for (int j = 0; j < 4; ++j) {
                uint32_t off = (e + j) * 128 + ((i * 2) ^ (((e + j) & 7) * 16));
                *(__half*)(sx + off) = h[j];
            }
        }
        __syncthreads();
        int4* dst = (int4*)g_X + (size_t)b * 4096 + e0 * 8;
        const int4* src = (const int4*)sx;
#pragma unroll
        for (int j = 0; j < 4; ++j)
            dst[j * 256 + tid] = src[j * 256 + tid];
    } else if (blk < 192) {
        // ---- ctrans: coeff -> g_Cs[k] swizzled ldsm-ready block ----
        const int k = blk - 128;
        char* dstb = (char*)g_Cs + (size_t)k * 8192;
        for (int idx = tid; idx < 4096; idx += 256) {
            int o = idx >> 6, i = idx & 63;
            float v = coeff[(size_t)(o * 64 + i) * 64 + k];
            uint32_t off = o * 128 + (((i >> 3) * 16) ^ ((o & 7) * 16)) + (i & 7) * 2;
            *(__half*)(dstb + off) = __float2half_rn(v);
        }
    } else {
        // ---- zero out ----
        const int idx = blk - 192;
        float4* o4 = (float4*)out;
        o4[idx * 512 + tid]       = make_float4(0.f, 0.f, 0.f, 0.f);
        o4[idx * 512 + 256 + tid] = make_float4(0.f, 0.f, 0.f, 0.f);
    }
}

// ---------------------------------------------------------------------------
// prep2: fused stage1 (split et-halves) + wsplit, role-interleaved.
//  grid 3072, 128 thr, 45KB dyn smem, 3 CTAs/SM.
//  blk%3==0 -> stage1 (sid=blk/3, 1024 blocks: b=sid>>5, kgrp=(sid>>1)&15, eth=sid&1)
//  else     -> wsplit (2048 blocks, 4 k-tiles each).
// ---------------------------------------------------------------------------
__global__ void __launch_bounds__(128, 3) prep2_kernel(const float* __restrict__ W) {
    extern __shared__ char smem[];
    const int blk = blockIdx.x, tid = threadIdx.x;
    const int lane = tid & 31, wid = tid >> 5;

    if (blk % 3 == 0) {
        // ================= stage1 role (half et-range) =================
        const int sid  = blk / 3;          // 0..1023
        const int eth  = sid & 1;
        const int kgrp = (sid >> 1) & 15;
        const int b    = sid >> 5;
        const int k    = kgrp * 4 + wid;
        const int et0  = eth * 8;

        const uint32_t sb  = smem_u32(smem);
        const uint32_t scb = sb;           // 32 KB: sC per warp 8KB
        const uint32_t sxp = sb + 32768;   // 3 x 4KB sX slices

        const int4* gc = (const int4*)g_Cs + (size_t)k * 512;
#pragma unroll
        for (int j = 0; j < 16; ++j)
            cp16(scb + wid * 8192 + (j * 32 + lane) * 16, gc + j * 32 + lane);
        const int4* gx = (const int4*)g_X + (size_t)b * 4096 + et0 * 256;
        cp16(sxp + tid * 16,        gx + tid);
        cp16(sxp + 2048 + tid * 16, gx + 128 + tid);
        CP_COMMIT();
        cp16(sxp + 4096 + tid * 16,        gx + 256 + tid);
        cp16(sxp + 4096 + 2048 + tid * 16, gx + 256 + 128 + tid);
        CP_COMMIT();

        CP_WAIT(1);
        __syncthreads();

        const int a_row  = (lane & 7) | (((lane >> 3) & 1) << 3);
        const int a_k16b = (lane >> 4) * 16;
        const int b_nr   = (lane & 7) | (((lane >> 4) & 1) << 3);
        const int b_k16b = ((lane >> 3) & 1) * 16;

        uint32_t a[4][4][4];
#pragma unroll
        for (int ot = 0; ot < 4; ++ot)
#pragma unroll
            for (int k16 = 0; k16 < 4; ++k16) {
                int r = ot * 16 + a_row;
                uint32_t off = scb + wid * 8192 + r * 128 +
                               ((k16 * 32 + a_k16b) ^ ((r & 7) * 16));
                ldsm4(a[ot][k16], off);
            }

        uint4* aOut = (uint4*)g_A;

#pragma unroll 1
        for (int e = 0; e < 8; ++e) {
            const int et = et0 + e;
            if (e > 0) {
                if (e < 7) { CP_WAIT(1); } else { CP_WAIT(0); }
                __syncthreads();
            }
            if (e + 2 < 8) {
                const int st = (e + 2) % 3;
                cp16(sxp + st * 4096 + tid * 16,        gx + (e + 2) * 256 + tid);
                cp16(sxp + st * 4096 + 2048 + tid * 16, gx + (e + 2) * 256 + 128 + tid);
                CP_COMMIT();
            }
            const uint32_t sxs = sxp + (e % 3) * 4096;

            float acc[4][4][4];
#pragma unroll
            for (int ot = 0; ot < 4; ++ot)
#pragma unroll
                for (int nt = 0; nt < 4; ++nt)
#pragma unroll
                    for (int j = 0; j < 4; ++j) acc[ot][nt][j] = 0.0f;

#pragma unroll
            for (int k16 = 0; k16 < 4; ++k16) {
                uint32_t bb[2][4];
#pragma unroll
                for (int p = 0; p < 2; ++p) {
                    int lr = p * 16 + b_nr;
                    uint32_t off = sxs + lr * 128 +
                                   ((k16 * 32 + b_k16b) ^ ((lr & 7) * 16));
                    ldsm4(bb[p], off);
                }
#pragma unroll
                for (int ot = 0; ot < 4; ++ot)
#pragma unroll
                    for (int nt = 0; nt < 4; ++nt)
                        mma_f16(acc[ot][nt], a[ot][k16], &bb[nt >> 1][(nt & 1) * 2]);
            }

#pragma unroll
            for (int ot = 0; ot < 4; ++ot) {
                const size_t mt = (size_t)(b * 4 + ot);
#pragma unroll
                for (int ntp = 0; ntp < 2; ++ntp) {
                    uint4 v;
                    v.x = f2h2(acc[ot][2 * ntp][0],     acc[ot][2 * ntp][1]);
                    v.y = f2h2(acc[ot][2 * ntp][2],     acc[ot][2 * ntp][3]);
                    v.z = f2h2(acc[ot][2 * ntp + 1][0], acc[ot][2 * ntp + 1][1]);
                    v.w = f2h2(acc[ot][2 * ntp + 1][2], acc[ot][2 * ntp + 1][3]);
                    size_t kt = (size_t)k * 32 + et * 2 + ntp;
                    aOut[(mt * 2048 + kt) * 32 + lane] = v;
                }
            }
        }
    } else {
        // ================= wsplit role =================
        const int idx = (blk / 3) * 2 + (blk % 3) - 1;   // 0..2047
        const int nb = idx & 15;
        const int kb0 = (idx >> 4) * 4;

        float (*s)[33] = (float (*)[33])smem;
        const int tx = lane, tg = wid;   // 4 warps

#pragma unroll 1
        for (int j = 0; j < 4; ++j) {
            const int kb = kb0 + j;
#pragma unroll
            for (int r = 0; r < 16; ++r) {
                int kr = tg + r * 4;
                s[kr][tx] = W[(size_t)(kb * 64 + kr) * DD + nb * 32 + tx];
            }
            __syncthreads();
#pragma unroll
            for (int r = 0; r < 8; ++r) {
                int nr = tg * 8 + r;
                __half2 h = __floats2half2_rn(s[tx * 2][nr], s[tx * 2 + 1][nr]);
                *(__half2*)&g_B[(size_t)(nb * 32 + nr) * KTOT + kb * 64 + tx * 2] = h;
            }
            __syncthreads();
        }
    }
}

// ---------------------------------------------------------------------------
// Stage 2: fp16 split-K GEMM (proven mainloop; SPLIT=32 for wave smoothing).
// ---------------------------------------------------------------------------
__global__ void __launch_bounds__(256, 3) gemm_kernel(float* __restrict__ out) {
    extern __shared__ char smem[];
    const uint32_t sb = (smem_u32(smem) + 1023) & ~1023u;

    const int tid  = threadIdx.x;
    const int lane = tid & 31;
    const int wid  = tid >> 5;
    const int n0 = blockIdx.x * BN;
    const int m0 = blockIdx.y * BM;
    const size_t k0 = (size_t)blockIdx.z * KPER;
    const int warp_m = (wid & 1) * 32;
    const int warp_n = (wid >> 1) * 32;

    const int mtq = tid >> 6;
    const int rq  = tid & 63;
    const size_t mtile0 = (size_t)(m0 >> 4);
    const size_t kt0 = k0 >> 4;
    const uint4* gAblk = (const uint4*)g_A + ((mtile0 + mtq) * 2048 + kt0) * 32;
    const int ktl0 = rq >> 5, w0 = rq & 31;
    const uint32_t aoff0 = (uint32_t)((ktl0 * 4 + mtq) * 512 + w0 * 16);
    const uint32_t aoff1 = (uint32_t)(((ktl0 + 2) * 4 + mtq) * 512 + w0 * 16);

    const int rB = tid >> 1, cB = (tid & 1) * 4;
    const __half* gB = g_B + (size_t)(n0 + rB) * KTOT + k0 + cB * 8;
    uint32_t swzB[4];
#pragma unroll
    for (int j = 0; j < 4; ++j)
        swzB[j] = 8192 + rB * 128 + (((cB + j) * 16) ^ ((rB & 7) * 16));

    const int b_nr   = (lane & 7) | (((lane >> 4) & 1) << 3);
    const int b_k16b = ((lane >> 3) & 1) * 16;
    const int mtb    = warp_m >> 4;

    float acc[2][4][4];
#pragma unroll
    for (int mt = 0; mt < 2; ++mt)
#pragma unroll
        for (int nt = 0; nt < 4; ++nt)
#pragma unroll
            for (int j = 0; j < 4; ++j) acc[mt][nt][j] = 0.0f;

    auto load_stage = [&](int c, int s) {
        const uint32_t base = sb + s * STAGE_BYTES;
        const uint4* src = gAblk + (size_t)c * 128;
        cp16(base + aoff0, src + rq);
        cp16(base + aoff1, src + rq + 64);
        const int ke = c * BK;
#pragma unroll
        for (int j = 0; j < 4; ++j)
            cp16(base + swzB[j], gB + ke + j * 8);
        CP_COMMIT();
    };

    load_stage(0, 0);
    load_stage(1, 1);

    int s = 0;
    for (int c = 0; c < NCH; ++c) {
        if (c + 1 < NCH) { CP_WAIT(1); } else { CP_WAIT(0); }
        __syncthreads();
        if (c + 2 < NCH) load_stage(c + 2, (c + 2) % NSTG);

        const uint32_t Ab = sb + s * STAGE_BYTES;

#pragma unroll
        for (int k16 = 0; k16 < 4; ++k16) {
            uint32_t a[2][4], bb[2][4];
#pragma unroll
            for (int mt = 0; mt < 2; ++mt)
                lds128(a[mt], Ab + (uint32_t)((k16 * 4 + mtb + mt) * 512 + lane * 16));
#pragma unroll
            for (int p = 0; p < 2; ++p) {
                int n = warp_n + p * 16 + b_nr;
                ldsm4(bb[p], Ab + 8192 + n * 128 + ((k16 * 32 + b_k16b) ^ ((n & 7) * 16)));
            }
#pragma unroll
            for (int mt = 0; mt < 2; ++mt)
#pragma unroll
                for (int nt = 0; nt < 4; ++nt)
                    mma_f16(acc[mt][nt], a[mt], &bb[nt >> 1][(nt & 1) * 2]);
        }
        s = (s + 1 == NSTG) ? 0 : s + 1;
    }

#pragma unroll
    for (int mt = 0; mt < 2; ++mt)
#pragma unroll
        for (int nt = 0; nt < 4; ++nt) {
            int r    = m0 + warp_m + mt * 16 + (lane >> 2);
            int ccol = n0 + warp_n + nt * 8 + (lane & 3) * 2;
            float* p0 = &out[(size_t)r * DD + ccol];
            float* p1 = &out[(size_t)(r + 8) * DD + ccol];
            atomicAdd(p0,     acc[mt][nt][0]);
            atomicAdd(p0 + 1, acc[mt][nt][1]);
            atomicAdd(p1,     acc[mt][nt][2]);
            atomicAdd(p1 + 1, acc[mt][nt][3]);
        }
}

extern "C" void kernel_launch(void* const* d_in, const int* in_sizes, int n_in,
                              void* d_out, int out_size) {
    const float* x     = (const float*)d_in[0];  // [32,64,512]
    const float* w     = (const float*)d_in[1];  // [64,512,512]
    const float* coeff = (const float*)d_in[2];  // [64,64,64]
    float* out = (float*)d_out;                  // [32,64,512]

    cudaFuncSetAttribute(gemm_kernel,  cudaFuncAttributeMaxDynamicSharedMemorySize, GEMM_SMEM);
    cudaFuncSetAttribute(prep1_kernel, cudaFuncAttributeMaxDynamicSharedMemorySize, P1_SMEM);
    cudaFuncSetAttribute(prep2_kernel, cudaFuncAttributeMaxDynamicSharedMemorySize, P2_SMEM);

    prep1_kernel<<<704, 256, P1_SMEM>>>(x, coeff, out);
    prep2_kernel<<<3072, 128, P2_SMEM>>>(w);
    gemm_kernel<<<dim3(DD / BN, MM / BM, SPLIT), 256, GEMM_SMEM>>>(out);
}

// round 17
// speedup vs baseline: 1.6746x; 1.0920x over previous
#include <cuda_runtime.h>
#include <cuda_fp16.h>
#include <cstdint>

// ---------------- problem constants ----------------
#define B_    32
#define DD    512
#define KK    64
#define KTOT  32768            // K*D : flattened reduction dim
#define MM    2048             // B*F_out
#define SPLIT 32
#define KPER  (KTOT / SPLIT)   // 1024
#define BK    64               // k elems per chunk
#define NCH   (KPER / BK)      // 16
#define BM    64
#define BN    128
#define NSTG  3
#define STAGE_BYTES 24576      // A frag-blocks 8K + B 16K
#define GEMM_SMEM   (NSTG * STAGE_BYTES + 1024)
#define P1_SMEM     16384      // xprep quarter-image build
#define P2_SMEM     46080      // sC 32K + 3 x 4K sX slices (+pad)

// ---------------- device scratch (no allocation) ----------------
// g_A: MMA-fragment-block layout. Block (m16-tile mt, k16-tile kt):
//   uint4 index (mt*2048 + kt)*32 + lane.
__device__ __half g_A[(size_t)MM * KTOT];          // 128 MB
__device__ __half g_B[(size_t)DD * KTOT];          // 32 MB  (W^T fp16, [d][k,e])
__device__ __half g_Cs[(size_t)KK * 4096];         // 512 KB (coeff swizzled ldsm blocks)
__device__ __half g_X[(size_t)B_ * 64 * 512];      // 2 MB   (x fp16, swizzled smem image per b)

// ---------------- helpers ----------------
__device__ __forceinline__ uint32_t smem_u32(const void* p) {
    uint32_t a;
    asm("{ .reg .u64 t; cvta.to.shared.u64 t, %1; cvt.u32.u64 %0, t; }" : "=r"(a) : "l"(p));
    return a;
}
__device__ __forceinline__ void cp16(uint32_t dst, const void* src) {
    asm volatile("cp.async.cg.shared.global [%0], [%1], 16;" :: "r"(dst), "l"(src));
}
#define CP_COMMIT() asm volatile("cp.async.commit_group;" ::: "memory")
#define CP_WAIT(n)  asm volatile("cp.async.wait_group %0;" :: "n"(n) : "memory")

__device__ __forceinline__ void ldsm4(uint32_t* r, uint32_t addr) {
    asm volatile("ldmatrix.sync.aligned.m8n8.x4.shared.b16 {%0,%1,%2,%3}, [%4];"
                 : "=r"(r[0]), "=r"(r[1]), "=r"(r[2]), "=r"(r[3]) : "r"(addr));
}
__device__ __forceinline__ void lds128(uint32_t* r, uint32_t addr) {
    asm volatile("ld.shared.v4.u32 {%0,%1,%2,%3}, [%4];"
                 : "=r"(r[0]), "=r"(r[1]), "=r"(r[2]), "=r"(r[3]) : "r"(addr));
}
__device__ __forceinline__ void mma_f16(float* c, const uint32_t* a, const uint32_t* b) {
    asm volatile(
        "mma.sync.aligned.m16n8k16.row.col.f32.f16.f16.f32 "
        "{%0,%1,%2,%3},{%4,%5,%6,%7},{%8,%9},{%0,%1,%2,%3};"
        : "+f"(c[0]), "+f"(c[1]), "+f"(c[2]), "+f"(c[3])
        : "r"(a[0]), "r"(a[1]), "r"(a[2]), "r"(a[3]), "r"(b[0]), "r"(b[1]));
}
__device__ __forceinline__ uint32_t f2h2(float a, float b) {
    __half2 h = __floats2half2_rn(a, b);
    return *reinterpret_cast<uint32_t*>(&h);
}
__device__ __forceinline__ void red2(float* p, float a, float b) {
    asm volatile("red.global.add.v2.f32 [%0], {%1, %2};"
                 :: "l"(p), "f"(a), "f"(b) : "memory");
}

// ---------------------------------------------------------------------------
// prep1: fused ctrans + xprep(split 4x).  grid 192, 256 thr.
//  blk [0,128): xprep quarter (b=blk>>2, e0=(blk&3)*128)
//  blk [128,192): ctrans(k=blk-128)
// ---------------------------------------------------------------------------
__global__ void __launch_bounds__(256) prep1_kernel(const float* __restrict__ x,
                                                    const float* __restrict__ coeff) {
    extern __shared__ char sx[];
    const int blk = blockIdx.x, tid = threadIdx.x;

    if (blk < 128) {
        // ---- xprep quarter: 128 e-rows of the swizzled fp16 image ----
        const int b  = blk >> 2;
        const int e0 = (blk & 3) * 128;
        const float* xb = x + (size_t)b * 64 * 512 + e0;
#pragma unroll 2
        for (int n = 0; n < 8; ++n) {
            int g = n * 256 + tid;
            int i = g >> 5, e = (g & 31) * 4;
            float4 v = *(const float4*)&xb[i * 512 + e];
            __half h[4] = {__float2half_rn(v.x), __float2half_rn(v.y),
                           __float2half_rn(v.z), __float2half_rn(v.w)};
#pragma unroll
            for (int j = 0; j < 4; ++j) {
                uint32_t off = (e + j) * 128 + ((i * 2) ^ (((e + j) & 7) * 16));
                *(__half*)(sx + off) = h[j];
            }
        }
        __syncthreads();
        int4* dst = (int4*)g_X + (size_t)b * 4096 + e0 * 8;
        const int4* src = (const int4*)sx;
#pragma unroll
        for (int j = 0; j < 4; ++j)
            dst[j * 256 + tid] = src[j * 256 + tid];
    } else {
        // ---- ctrans: coeff -> g_Cs[k] swizzled ldsm-ready block ----
        const int k = blk - 128;
        char* dstb = (char*)g_Cs + (size_t)k * 8192;
        for (int idx = tid; idx < 4096; idx += 256) {
            int o = idx >> 6, i = idx & 63;
            float v = coeff[(size_t)(o * 64 + i) * 64 + k];
            uint32_t off = o * 128 + (((i >> 3) * 16) ^ ((o & 7) * 16)) + (i & 7) * 2;
            *(__half*)(dstb + off) = __float2half_rn(v);
        }
    }
}

// ---------------------------------------------------------------------------
// prep2: fused stage1 (et quarters) + wsplit + zero, role-interleaved.
//  grid 4128, 128 thr, 45KB dyn smem, 3 CTAs/SM.
//  blk<4096: blk&1==0 -> stage1 (sid=blk>>1, 2048 blocks)
//            blk&1==1 -> wsplit (idx=blk>>1, 2048 blocks)
//  blk>=4096 -> zero role (32 blocks)
// ---------------------------------------------------------------------------
__global__ void __launch_bounds__(128, 3) prep2_kernel(const float* __restrict__ W,
                                                       float* __restrict__ out) {
    extern __shared__ char smem[];
    const int blk = blockIdx.x, tid = threadIdx.x;
    const int lane = tid & 31, wid = tid >> 5;

    if (blk >= 4096) {
        // ================= zero role =================
        const int idx = blk - 4096;     // 0..31
        float4* o4 = (float4*)out + (size_t)idx * 8192;
#pragma unroll
        for (int j = 0; j < 64; ++j)
            o4[j * 128 + tid] = make_float4(0.f, 0.f, 0.f, 0.f);
        return;
    }

    if ((blk & 1) == 0) {
        // ================= stage1 role (et quarter) =================
        const int sid  = blk >> 1;         // 0..2047
        const int etq  = sid & 3;
        const int kgrp = (sid >> 2) & 15;
        const int b    = sid >> 6;
        const int k    = kgrp * 4 + wid;
        const int et0  = etq * 4;

        const uint32_t sb  = smem_u32(smem);
        const uint32_t scb = sb;           // 32 KB: sC per warp 8KB
        const uint32_t sxp = sb + 32768;   // 3 x 4KB sX slices

        const int4* gc = (const int4*)g_Cs + (size_t)k * 512;
#pragma unroll
        for (int j = 0; j < 16; ++j)
            cp16(scb + wid * 8192 + (j * 32 + lane) * 16, gc + j * 32 + lane);
        const int4* gx = (const int4*)g_X + (size_t)b * 4096 + et0 * 256;
        cp16(sxp + tid * 16,        gx + tid);
        cp16(sxp + 2048 + tid * 16, gx + 128 + tid);
        CP_COMMIT();
        cp16(sxp + 4096 + tid * 16,        gx + 256 + tid);
        cp16(sxp + 4096 + 2048 + tid * 16, gx + 256 + 128 + tid);
        CP_COMMIT();

        CP_WAIT(1);
        __syncthreads();

        const int a_row  = (lane & 7) | (((lane >> 3) & 1) << 3);
        const int a_k16b = (lane >> 4) * 16;
        const int b_nr   = (lane & 7) | (((lane >> 4) & 1) << 3);
        const int b_k16b = ((lane >> 3) & 1) * 16;

        uint32_t a[4][4][4];
#pragma unroll
        for (int ot = 0; ot < 4; ++ot)
#pragma unroll
            for (int k16 = 0; k16 < 4; ++k16) {
                int r = ot * 16 + a_row;
                uint32_t off = scb + wid * 8192 + r * 128 +
                               ((k16 * 32 + a_k16b) ^ ((r & 7) * 16));
                ldsm4(a[ot][k16], off);
            }

        uint4* aOut = (uint4*)g_A;

#pragma unroll 1
        for (int e = 0; e < 4; ++e) {
            const int et = et0 + e;
            if (e > 0) {
                if (e < 3) { CP_WAIT(1); } else { CP_WAIT(0); }
                __syncthreads();
            }
            if (e + 2 < 4) {
                const int st = (e + 2) % 3;
                cp16(sxp + st * 4096 + tid * 16,        gx + (e + 2) * 256 + tid);
                cp16(sxp + st * 4096 + 2048 + tid * 16, gx + (e + 2) * 256 + 128 + tid);
                CP_COMMIT();
            }
            const uint32_t sxs = sxp + (e % 3) * 4096;

            float acc[4][4][4];
#pragma unroll
            for (int ot = 0; ot < 4; ++ot)
#pragma unroll
                for (int nt = 0; nt < 4; ++nt)
#pragma unroll
                    for (int j = 0; j < 4; ++j) acc[ot][nt][j] = 0.0f;

#pragma unroll
            for (int k16 = 0; k16 < 4; ++k16) {
                uint32_t bb[2][4];
#pragma unroll
                for (int p = 0; p < 2; ++p) {
                    int lr = p * 16 + b_nr;
                    uint32_t off = sxs + lr * 128 +
                                   ((k16 * 32 + b_k16b) ^ ((lr & 7) * 16));
                    ldsm4(bb[p], off);
                }
#pragma unroll
                for (int ot = 0; ot < 4; ++ot)
#pragma unroll
                    for (int nt = 0; nt < 4; ++nt)
                        mma_f16(acc[ot][nt], a[ot][k16], &bb[nt >> 1][(nt & 1) * 2]);
            }

#pragma unroll
            for (int ot = 0; ot < 4; ++ot) {
                const size_t mt = (size_t)(b * 4 + ot);
#pragma unroll
                for (int ntp = 0; ntp < 2; ++ntp) {
                    uint4 v;
                    v.x = f2h2(acc[ot][2 * ntp][0],     acc[ot][2 * ntp][1]);
                    v.y = f2h2(acc[ot][2 * ntp][2],     acc[ot][2 * ntp][3]);
                    v.z = f2h2(acc[ot][2 * ntp + 1][0], acc[ot][2 * ntp + 1][1]);
                    v.w = f2h2(acc[ot][2 * ntp + 1][2], acc[ot][2 * ntp + 1][3]);
                    size_t kt = (size_t)k * 32 + et * 2 + ntp;
                    aOut[(mt * 2048 + kt) * 32 + lane] = v;
                }
            }
        }
    } else {
        // ================= wsplit role =================
        const int idx = blk >> 1;          // 0..2047
        const int nb = idx & 15;
        const int kb0 = (idx >> 4) * 4;

        float (*s)[33] = (float (*)[33])smem;
        const int tx = lane, tg = wid;   // 4 warps

#pragma unroll 1
        for (int j = 0; j < 4; ++j) {
            const int kb = kb0 + j;
#pragma unroll
            for (int r = 0; r < 16; ++r) {
                int kr = tg + r * 4;
                s[kr][tx] = W[(size_t)(kb * 64 + kr) * DD + nb * 32 + tx];
            }
            __syncthreads();
#pragma unroll
            for (int r = 0; r < 8; ++r) {
                int nr = tg * 8 + r;
                __half2 h = __floats2half2_rn(s[tx * 2][nr], s[tx * 2 + 1][nr]);
                *(__half2*)&g_B[(size_t)(nb * 32 + nr) * KTOT + kb * 64 + tx * 2] = h;
            }
            __syncthreads();
        }
    }
}

// ---------------------------------------------------------------------------
// Stage 2: fp16 split-K GEMM (proven mainloop; red.v2 epilogue).
// ---------------------------------------------------------------------------
__global__ void __launch_bounds__(256, 3) gemm_kernel(float* __restrict__ out) {
    extern __shared__ char smem[];
    const uint32_t sb = (smem_u32(smem) + 1023) & ~1023u;

    const int tid  = threadIdx.x;
    const int lane = tid & 31;
    const int wid  = tid >> 5;
    const int n0 = blockIdx.x * BN;
    const int m0 = blockIdx.y * BM;
    const size_t k0 = (size_t)blockIdx.z * KPER;
    const int warp_m = (wid & 1) * 32;
    const int warp_n = (wid >> 1) * 32;

    const int mtq = tid >> 6;
    const int rq  = tid & 63;
    const size_t mtile0 = (size_t)(m0 >> 4);
    const size_t kt0 = k0 >> 4;
    const uint4* gAblk = (const uint4*)g_A + ((mtile0 + mtq) * 2048 + kt0) * 32;
    const int ktl0 = rq >> 5, w0 = rq & 31;
    const uint32_t aoff0 = (uint32_t)((ktl0 * 4 + mtq) * 512 + w0 * 16);
    const uint32_t aoff1 = (uint32_t)(((ktl0 + 2) * 4 + mtq) * 512 + w0 * 16);

    const int rB = tid >> 1, cB = (tid & 1) * 4;
    const __half* gB = g_B + (size_t)(n0 + rB) * KTOT + k0 + cB * 8;
    uint32_t swzB[4];
#pragma unroll
    for (int j = 0; j < 4; ++j)
        swzB[j] = 8192 + rB * 128 + (((cB + j) * 16) ^ ((rB & 7) * 16));

    const int b_nr   = (lane & 7) | (((lane >> 4) & 1) << 3);
    const int b_k16b = ((lane >> 3) & 1) * 16;
    const int mtb    = warp_m >> 4;

    float acc[2][4][4];
#pragma unroll
    for (int mt = 0; mt < 2; ++mt)
#pragma unroll
        for (int nt = 0; nt < 4; ++nt)
#pragma unroll
            for (int j = 0; j < 4; ++j) acc[mt][nt][j] = 0.0f;

    auto load_stage = [&](int c, int s) {
        const uint32_t base = sb + s * STAGE_BYTES;
        const uint4* src = gAblk + (size_t)c * 128;
        cp16(base + aoff0, src + rq);
        cp16(base + aoff1, src + rq + 64);
        const int ke = c * BK;
#pragma unroll
        for (int j = 0; j < 4; ++j)
            cp16(base + swzB[j], gB + ke + j * 8);
        CP_COMMIT();
    };

    load_stage(0, 0);
    load_stage(1, 1);

    int s = 0;
    for (int c = 0; c < NCH; ++c) {
        if (c + 1 < NCH) { CP_WAIT(1); } else { CP_WAIT(0); }
        __syncthreads();
        if (c + 2 < NCH) load_stage(c + 2, (c + 2) % NSTG);

        const uint32_t Ab = sb + s * STAGE_BYTES;

#pragma unroll
        for (int k16 = 0; k16 < 4; ++k16) {
            uint32_t a[2][4], bb[2][4];
#pragma unroll
            for (int mt = 0; mt < 2; ++mt)
                lds128(a[mt], Ab + (uint32_t)((k16 * 4 + mtb + mt) * 512 + lane * 16));
#pragma unroll
            for (int p = 0; p < 2; ++p) {
                int n = warp_n + p * 16 + b_nr;
                ldsm4(bb[p], Ab + 8192 + n * 128 + ((k16 * 32 + b_k16b) ^ ((n & 7) * 16)));
            }
#pragma unroll
            for (int mt = 0; mt < 2; ++mt)
#pragma unroll
                for (int nt = 0; nt < 4; ++nt)
                    mma_f16(acc[mt][nt], a[mt], &bb[nt >> 1][(nt & 1) * 2]);
        }
        s = (s + 1 == NSTG) ? 0 : s + 1;
    }

#pragma unroll
    for (int mt = 0; mt < 2; ++mt)
#pragma unroll
        for (int nt = 0; nt < 4; ++nt) {
            int r    = m0 + warp_m + mt * 16 + (lane >> 2);
            int ccol = n0 + warp_n + nt * 8 + (lane & 3) * 2;
            red2(&out[(size_t)r * DD + ccol],       acc[mt][nt][0], acc[mt][nt][1]);
            red2(&out[(size_t)(r + 8) * DD + ccol], acc[mt][nt][2], acc[mt][nt][3]);
        }
}

extern "C" void kernel_launch(void* const* d_in, const int* in_sizes, int n_in,
                              void* d_out, int out_size) {
    const float* x     = (const float*)d_in[0];  // [32,64,512]
    const float* w     = (const float*)d_in[1];  // [64,512,512]
    const float* coeff = (const float*)d_in[2];  // [64,64,64]
    float* out = (float*)d_out;                  // [32,64,512]

    cudaFuncSetAttribute(gemm_kernel,  cudaFuncAttributeMaxDynamicSharedMemorySize, GEMM_SMEM);
    cudaFuncSetAttribute(prep1_kernel, cudaFuncAttributeMaxDynamicSharedMemorySize, P1_SMEM);
    cudaFuncSetAttribute(prep2_kernel, cudaFuncAttributeMaxDynamicSharedMemorySize, P2_SMEM);

    prep1_kernel<<<192, 256, P1_SMEM>>>(x, coeff);
    prep2_kernel<<<4128, 128, P2_SMEM>>>(w, out);
    gemm_kernel<<<dim3(DD / BN, MM / BM, SPLIT), 256, GEMM_SMEM>>>(out);
}